// round 8
// baseline (speedup 1.0000x reference)
#include <cuda_runtime.h>
#include <math.h>
#include <stdint.h>
#include <limits.h>

#define H    128
#define NB   64
#define SQ   32
#define SD   256
#define NQTOK (NB*SQ)   // 2048
#define NDTOK (NB*SD)   // 16384

// quantization: t = round(16000*v) = h*128 + l
#define QSCALE 16000.0f
#define SCORE_SCALE (128.0f / (16000.0f * 16000.0f))   // int->score

// ---------------- scratch (allocation-free rule) ----------------
__device__ int8_t g_qh[NQTOK*H];
__device__ int8_t g_ql[NQTOK*H];
__device__ int8_t g_dh[NDTOK*H];
__device__ int8_t g_dl[NDTOK*H];
__device__ float g_sumq[NB*H];
__device__ float g_sumd[NB*H];
__device__ float g_scores[NB*NB];
__device__ unsigned g_done;       // zero-init; last CTA resets -> replay-safe

// ---------------- helpers ----------------
__device__ __forceinline__ uint32_t smem_u32(const void* p) {
    uint32_t a;
    asm("{ .reg .u64 t; cvta.to.shared.u64 t, %1; cvt.u32.u64 %0, t; }" : "=r"(a) : "l"(p));
    return a;
}
// rows of 128B (8 chunks x 16B); phys chunk = c ^ (row & 7)
__device__ __forceinline__ uint32_t swz8(uint32_t base, int row, int chunk) {
    return base + row * 128 + ((chunk ^ (row & 7)) << 4);
}
__device__ __forceinline__ void ldsm_x4(uint32_t& r0, uint32_t& r1, uint32_t& r2, uint32_t& r3,
                                        uint32_t addr) {
    asm volatile("ldmatrix.sync.aligned.m8n8.x4.shared.b16 {%0,%1,%2,%3}, [%4];"
                 : "=r"(r0), "=r"(r1), "=r"(r2), "=r"(r3) : "r"(addr));
}
__device__ __forceinline__ void mma_s8(int& d0, int& d1, int& d2, int& d3,
                                       uint32_t a0, uint32_t a1, uint32_t a2, uint32_t a3,
                                       uint32_t b0, uint32_t b1) {
    asm volatile("mma.sync.aligned.m16n8k32.row.col.s32.s8.s8.s32 "
                 "{%0,%1,%2,%3}, {%4,%5,%6,%7}, {%8,%9}, {%0,%1,%2,%3};"
                 : "+r"(d0), "+r"(d1), "+r"(d2), "+r"(d3)
                 : "r"(a0), "r"(a1), "r"(a2), "r"(a3), "r"(b0), "r"(b1));
}
#define CP_ASYNC16(dst, src) \
    asm volatile("cp.async.cg.shared.global [%0], [%1], 16;" :: "r"(dst), "l"(src))
#define CP_COMMIT() asm volatile("cp.async.commit_group;" ::: "memory")
#define CP_WAIT0()  asm volatile("cp.async.wait_group 0;" ::: "memory")

// ---------------------------------------------------------------------------
// Kernel 1: normalize + mask + int8 hi/lo quantize + per-batch unmasked sums.
// blocks [0,256) = q tokens, [256, 2304) = d tokens. 8 tokens per block.
// ---------------------------------------------------------------------------
__global__ void normsplit_all(const float* __restrict__ qin, const float* __restrict__ din,
                              const int* __restrict__ qm, const int* __restrict__ dm)
{
    __shared__ float red[8 * 128];
    const int blk  = blockIdx.x;
    const int tid  = threadIdx.x;
    const int wid  = tid >> 5;
    const int lane = tid & 31;

    const float* in;  const int* mask;  int8_t* outh;  int8_t* outl;  float* sums;
    int tpb, tokbase;
    if (blk < 256) { in = qin; mask = qm; outh = g_qh; outl = g_ql; sums = g_sumq; tpb = SQ; tokbase = blk * 8; }
    else           { in = din; mask = dm; outh = g_dh; outl = g_dl; sums = g_sumd; tpb = SD; tokbase = (blk - 256) * 8; }

    const int tok = tokbase + wid;
    float4 v = ((const float4*)in)[tok * 32 + lane];
    float ss = v.x*v.x + v.y*v.y + v.z*v.z + v.w*v.w;
    #pragma unroll
    for (int o = 16; o; o >>= 1) ss += __shfl_xor_sync(0xffffffffu, ss, o);
    float scale = 1.0f / fmaxf(sqrtf(ss), 1e-12f);
    v.x *= scale; v.y *= scale; v.z *= scale; v.w *= scale;

    red[wid * 128 + lane * 4 + 0] = v.x;
    red[wid * 128 + lane * 4 + 1] = v.y;
    red[wid * 128 + lane * 4 + 2] = v.z;
    red[wid * 128 + lane * 4 + 3] = v.w;

    float m = mask[tok] ? QSCALE : 0.0f;
    int t0 = __float2int_rn(v.x * m);
    int t1 = __float2int_rn(v.y * m);
    int t2 = __float2int_rn(v.z * m);
    int t3 = __float2int_rn(v.w * m);
    int h0 = (t0 + 64) >> 7, l0 = t0 - (h0 << 7);
    int h1 = (t1 + 64) >> 7, l1 = t1 - (h1 << 7);
    int h2 = (t2 + 64) >> 7, l2 = t2 - (h2 << 7);
    int h3 = (t3 + 64) >> 7, l3 = t3 - (h3 << 7);
    uint32_t hw = (h0 & 0xFF) | ((h1 & 0xFF) << 8) | ((h2 & 0xFF) << 16) | ((h3 & 0xFF) << 24);
    uint32_t lw = (l0 & 0xFF) | ((l1 & 0xFF) << 8) | ((l2 & 0xFF) << 16) | ((l3 & 0xFF) << 24);
    ((uint32_t*)outh)[tok * 32 + lane] = hw;
    ((uint32_t*)outl)[tok * 32 + lane] = lw;

    __syncthreads();
    if (tid < 128) {
        float s = 0.f;
        #pragma unroll
        for (int w = 0; w < 8; w++) s += red[w * 128 + tid];
        atomicAdd(&sums[(tokbase / tpb) * 128 + tid], s);
    }
}

// ---------------------------------------------------------------------------
// Kernel 2: int8 3-pass max-GEMM (exact int16 sans ll term) + fused final.
// Grid (16, 8): CTA = (q panel p: 128 rows, d slice s: 2048 rows).
// Q hi+lo resident (32 KB); D subtiles (hi+lo, 32 KB) double-buffered.
// 8 warps, 64x32 warp tiles, m16n8k32 s8 IMMA, int32 accum.
// score_int = (accH << 7) + accX  (exact), max in integer domain.
// ---------------------------------------------------------------------------
#define T_BYTES  (128 * 128)     // one 128x128 int8 tile
#define SRED_OFF (6 * T_BYTES)
#define SMEM_BYTES (SRED_OFF + 16 * 16 * 4)

__device__ __forceinline__ void cp_tile8(uint32_t dst_u32, const int8_t* __restrict__ src, int tid)
{
    #pragma unroll
    for (int i = 0; i < 4; i++) {
        int id  = i * 256 + tid;       // 1024 chunks: 128 rows x 8 chunks
        int row = id >> 3;
        int ck  = id & 7;
        CP_ASYNC16(swz8(dst_u32, row, ck), src + row * 128 + ck * 16);
    }
}

__global__ __launch_bounds__(256, 1) void maxgemm_kernel(float* __restrict__ out)
{
    extern __shared__ char sm[];
    const uint32_t sQh = smem_u32(sm);
    const uint32_t sQl = sQh + T_BYTES;
    const uint32_t sD0h = sQh + 2 * T_BYTES;
    const uint32_t sD0l = sQh + 3 * T_BYTES;
    const uint32_t sD1h = sQh + 4 * T_BYTES;
    const uint32_t sD1l = sQh + 5 * T_BYTES;
    int* sred = (int*)(sm + SRED_OFF);   // [16 subtiles][4 al][4 wn]

    __shared__ bool  s_last;
    __shared__ float s_avgq[64], s_avgd[64], s_red[64];

    const int p    = blockIdx.x;     // q panel 0..15
    const int s    = blockIdx.y;     // d slice 0..7
    const int tid  = threadIdx.x;    // 256
    const int wid  = tid >> 5;
    const int lane = tid & 31;
    const int wm   = wid >> 2;       // 0..1 -> 64 q rows
    const int wn   = wid & 3;        // 0..3 -> 32 d rows

    // ldmatrix per-lane source row/chunk offsets (16B chunks; k32 = 2 chunks)
    const int a_row = ((lane >> 3) & 1) * 8 + (lane & 7);
    const int a_chk = lane >> 4;
    const int b_row = (lane >> 4) * 8 + (lane & 7);
    const int b_chk = (lane >> 3) & 1;

    const int8_t* dhbase = g_dh + (size_t)(s * 8) * 256 * H;
    const int8_t* dlbase = g_dl + (size_t)(s * 8) * 256 * H;

    cp_tile8(sQh, g_qh + (size_t)p * 128 * H, tid);
    cp_tile8(sQl, g_ql + (size_t)p * 128 * H, tid);
    cp_tile8(sD0h, dhbase, tid);
    cp_tile8(sD0l, dlbase, tid);
    CP_COMMIT();
    CP_WAIT0();
    __syncthreads();

    #pragma unroll 1
    for (int t = 0; t < 16; t++) {
        const uint32_t sBh = (t & 1) ? sD1h : sD0h;
        const uint32_t sBl = (t & 1) ? sD1l : sD0l;
        if (t < 15) {
            cp_tile8((t & 1) ? sD0h : sD1h, dhbase + (size_t)(t + 1) * 128 * H, tid);
            cp_tile8((t & 1) ? sD0l : sD1l, dlbase + (size_t)(t + 1) * 128 * H, tid);
            CP_COMMIT();
        }

        int accH[4][4][4], accX[4][4][4];
        #pragma unroll
        for (int mt = 0; mt < 4; mt++)
            #pragma unroll
            for (int nb = 0; nb < 4; nb++)
                #pragma unroll
                for (int r = 0; r < 4; r++) { accH[mt][nb][r] = 0; accX[mt][nb][r] = 0; }

        #pragma unroll
        for (int ks = 0; ks < 4; ks++) {
            uint32_t Ah[4][4], Al[4][4], Bh[2][4], Bl[2][4];
            #pragma unroll
            for (int mt = 0; mt < 4; mt++) {
                ldsm_x4(Ah[mt][0], Ah[mt][1], Ah[mt][2], Ah[mt][3],
                        swz8(sQh, wm * 64 + mt * 16 + a_row, 2 * ks + a_chk));
                ldsm_x4(Al[mt][0], Al[mt][1], Al[mt][2], Al[mt][3],
                        swz8(sQl, wm * 64 + mt * 16 + a_row, 2 * ks + a_chk));
            }
            #pragma unroll
            for (int np = 0; np < 2; np++) {
                ldsm_x4(Bh[np][0], Bh[np][1], Bh[np][2], Bh[np][3],
                        swz8(sBh, wn * 32 + np * 16 + b_row, 2 * ks + b_chk));
                ldsm_x4(Bl[np][0], Bl[np][1], Bl[np][2], Bl[np][3],
                        swz8(sBl, wn * 32 + np * 16 + b_row, 2 * ks + b_chk));
            }
            #pragma unroll
            for (int mt = 0; mt < 4; mt++)
                #pragma unroll
                for (int np = 0; np < 2; np++) {
                    // hh -> accH
                    mma_s8(accH[mt][2*np][0], accH[mt][2*np][1], accH[mt][2*np][2], accH[mt][2*np][3],
                           Ah[mt][0], Ah[mt][1], Ah[mt][2], Ah[mt][3], Bh[np][0], Bh[np][1]);
                    mma_s8(accH[mt][2*np+1][0], accH[mt][2*np+1][1], accH[mt][2*np+1][2], accH[mt][2*np+1][3],
                           Ah[mt][0], Ah[mt][1], Ah[mt][2], Ah[mt][3], Bh[np][2], Bh[np][3]);
                    // lh -> accX
                    mma_s8(accX[mt][2*np][0], accX[mt][2*np][1], accX[mt][2*np][2], accX[mt][2*np][3],
                           Al[mt][0], Al[mt][1], Al[mt][2], Al[mt][3], Bh[np][0], Bh[np][1]);
                    mma_s8(accX[mt][2*np+1][0], accX[mt][2*np+1][1], accX[mt][2*np+1][2], accX[mt][2*np+1][3],
                           Al[mt][0], Al[mt][1], Al[mt][2], Al[mt][3], Bh[np][2], Bh[np][3]);
                    // hl -> accX
                    mma_s8(accX[mt][2*np][0], accX[mt][2*np][1], accX[mt][2*np][2], accX[mt][2*np][3],
                           Ah[mt][0], Ah[mt][1], Ah[mt][2], Ah[mt][3], Bl[np][0], Bl[np][1]);
                    mma_s8(accX[mt][2*np+1][0], accX[mt][2*np+1][1], accX[mt][2*np+1][2], accX[mt][2*np+1][3],
                           Ah[mt][0], Ah[mt][1], Ah[mt][2], Ah[mt][3], Bl[np][2], Bl[np][3]);
                }
        }

        // ---- epilogue (integer max): subtile t -> batch b = s*8 + (t>>1) ----
        int m0 = INT_MIN, m1 = INT_MIN;   // a_local wm*2, wm*2+1
        #pragma unroll
        for (int mt = 0; mt < 4; mt++) {
            int mm = INT_MIN;
            #pragma unroll
            for (int nb = 0; nb < 4; nb++)
                #pragma unroll
                for (int r = 0; r < 4; r++) {
                    int sc = (accH[mt][nb][r] << 7) + accX[mt][nb][r];
                    mm = max(mm, sc);
                }
            if (mt < 2) m0 = max(m0, mm); else m1 = max(m1, mm);
        }
        #pragma unroll
        for (int o = 16; o; o >>= 1) {
            m0 = max(m0, __shfl_xor_sync(0xffffffffu, m0, o));
            m1 = max(m1, __shfl_xor_sync(0xffffffffu, m1, o));
        }
        if (lane == 0) {
            sred[t * 16 + (wm * 2 + 0) * 4 + wn] = m0;
            sred[t * 16 + (wm * 2 + 1) * 4 + wn] = m1;
        }

        CP_WAIT0();
        __syncthreads();
    }

    if (tid < 32) {
        int bl = tid >> 2;      // batch-local 0..7
        int al = tid & 3;       // a-local 0..3
        int v = INT_MIN;
        #pragma unroll
        for (int st = 0; st < 2; st++)
            #pragma unroll
            for (int w = 0; w < 4; w++)
                v = max(v, sred[(bl * 2 + st) * 16 + al * 4 + w]);
        g_scores[(p * 4 + al) * NB + (s * 8 + bl)] = (float)v * SCORE_SCALE;
    }

    // ---- last-CTA fused final reduction ----
    __threadfence();
    __syncthreads();
    if (tid == 0) s_last = (atomicAdd(&g_done, 1u) == 127u);
    __syncthreads();
    if (!s_last) return;
    if (tid == 0) g_done = 0;

    for (int b = wid; b < NB; b += 8) {
        float4 vq = ((const float4*)g_sumq)[b * 32 + lane];
        float4 vd = ((const float4*)g_sumd)[b * 32 + lane];
        float sq = vq.x*vq.x + vq.y*vq.y + vq.z*vq.z + vq.w*vq.w;
        float sd = vd.x*vd.x + vd.y*vd.y + vd.z*vd.z + vd.w*vd.w;
        #pragma unroll
        for (int o = 16; o; o >>= 1) {
            sq += __shfl_xor_sync(0xffffffffu, sq, o);
            sd += __shfl_xor_sync(0xffffffffu, sd, o);
        }
        if (lane == 0) {
            s_avgq[b] = (sq - (float)SQ) * (1.0f / ((float)SQ * (SQ - 1)));
            s_avgd[b] = (sd - (float)SD) * (1.0f / ((float)SD * (SD - 1)));
        }
    }
    __syncthreads();

    #pragma unroll
    for (int r = 0; r < 8; r++) {
        int a = wid * 8 + r;
        float v0 = __ldcg(&g_scores[a * NB + lane]);
        float v1 = __ldcg(&g_scores[a * NB + 32 + lane]);
        float mx = fmaxf(v0, v1);
        #pragma unroll
        for (int o = 16; o; o >>= 1) mx = fmaxf(mx, __shfl_xor_sync(0xffffffffu, mx, o));
        float sum = expf(v0 - mx) + expf(v1 - mx);
        #pragma unroll
        for (int o = 16; o; o >>= 1) sum += __shfl_xor_sync(0xffffffffu, sum, o);
        if (lane == 0) {
            float diag = __ldcg(&g_scores[a * NB + a]);
            s_red[a] = mx + logf(sum) - diag + s_avgq[a] + s_avgd[a];
        }
    }
    __syncthreads();
    if (tid < 32) {
        float v = s_red[tid] + s_red[tid + 32];
        #pragma unroll
        for (int o = 16; o; o >>= 1) v += __shfl_xor_sync(0xffffffffu, v, o);
        if (tid == 0) out[0] = v * (1.0f / NB);
    }
}

// ---------------------------------------------------------------------------
extern "C" void kernel_launch(void* const* d_in, const int* in_sizes, int n_in,
                              void* d_out, int out_size)
{
    const float* q_emb  = (const float*)d_in[0];
    const float* d_emb  = (const float*)d_in[1];
    const int*   q_mask = (const int*)  d_in[2];
    const int*   d_mask = (const int*)  d_in[3];
    float*       out    = (float*)d_out;

    cudaFuncSetAttribute(maxgemm_kernel,
                         cudaFuncAttributeMaxDynamicSharedMemorySize, SMEM_BYTES);

    float *sumq, *sumd;
    cudaGetSymbolAddress((void**)&sumq, g_sumq);
    cudaGetSymbolAddress((void**)&sumd, g_sumd);

    cudaMemsetAsync(sumq, 0, NB * H * sizeof(float));
    cudaMemsetAsync(sumd, 0, NB * H * sizeof(float));
    normsplit_all<<<256 + 2048, 256>>>(q_emb, d_emb, q_mask, d_mask);
    maxgemm_kernel<<<dim3(16, 8), 256, SMEM_BYTES>>>(out);
}

// round 9
// speedup vs baseline: 2.9807x; 2.9807x over previous
#include <cuda_runtime.h>
#include <math.h>
#include <stdint.h>

#define H    128
#define NB   64
#define SQ   32
#define SD   256
#define NQTOK (NB*SQ)   // 2048
#define NDTOK (NB*SD)   // 16384
#define QLK_N (NQTOK/8)    // 256
#define DLK_N (NDTOK/32)   // 512

// ---------------- scratch (single struct -> one memset) ----------------
struct Scratch {
    float qt[NQTOK*H];      // compacted q (tf32, masked); padding stays zero
    float dt[NDTOK*H];      // compacted d
    float sumq[NB*H];
    float sumd[NB*H];
    float scores[NB*NB];    // atomicMax (int view), init 0 = mask floor
    int qcnt[NB], dcnt[NB];
    int qcur[NB], dcur[NB];
    int qlk[QLK_N];         // 8-row group -> batch a
    int dlk[DLK_N];         // 32-col group -> batch b
    int qoff[NB], doff[NB];
    int nqt, ndt;           // active tile counts
    unsigned done;
};
__device__ Scratch G;
__device__ float g_stage[(NQTOK+NDTOK)*H];   // normalized+masked tf32, uncompacted

// ---------------- helpers ----------------
__device__ __forceinline__ uint32_t smem_u32(const void* p) {
    uint32_t a;
    asm("{ .reg .u64 t; cvta.to.shared.u64 t, %1; cvt.u32.u64 %0, t; }" : "=r"(a) : "l"(p));
    return a;
}
__device__ __forceinline__ float f2tf32(float x) {
    uint32_t r;
    asm("cvt.rna.tf32.f32 %0, %1;" : "=r"(r) : "f"(x));
    return __uint_as_float(r);
}
__device__ __forceinline__ void mma_tf32(float& d0, float& d1, float& d2, float& d3,
                                         uint32_t a0, uint32_t a1, uint32_t a2, uint32_t a3,
                                         uint32_t b0, uint32_t b1) {
    asm volatile("mma.sync.aligned.m16n8k8.row.col.f32.tf32.tf32.f32 "
                 "{%0,%1,%2,%3}, {%4,%5,%6,%7}, {%8,%9}, {%0,%1,%2,%3};"
                 : "+f"(d0), "+f"(d1), "+f"(d2), "+f"(d3)
                 : "r"(a0), "r"(a1), "r"(a2), "r"(a3), "r"(b0), "r"(b1));
}
#define CP_ASYNC16(dst, src) \
    asm volatile("cp.async.cg.shared.global [%0], [%1], 16;" :: "r"(dst), "l"(src))
#define CP_COMMIT() asm volatile("cp.async.commit_group;" ::: "memory")
#define CP_WAIT0()  asm volatile("cp.async.wait_group 0;" ::: "memory")
#define CP_WAIT1()  asm volatile("cp.async.wait_group 1;" ::: "memory")

// ---------------------------------------------------------------------------
// Kernel 1: normalize + mask + tf32 -> g_stage; per-batch sums + unmasked counts.
// blocks [0,256) = q tokens, [256,2304) = d. 8 tokens (one batch) per block.
// ---------------------------------------------------------------------------
__global__ void norm_count(const float* __restrict__ qin, const float* __restrict__ din,
                           const int* __restrict__ qm, const int* __restrict__ dm)
{
    __shared__ float red[8 * 128];
    __shared__ int s_cnt;
    const int blk  = blockIdx.x;
    const int tid  = threadIdx.x;
    const int wid  = tid >> 5;
    const int lane = tid & 31;

    const float* in; const int* mask; float* sums; int* cnt; int tpb, tokbase, stbase;
    if (blk < 256) { in = qin; mask = qm; sums = G.sumq; cnt = G.qcnt; tpb = SQ; tokbase = blk * 8; stbase = 0; }
    else           { in = din; mask = dm; sums = G.sumd; cnt = G.dcnt; tpb = SD; tokbase = (blk - 256) * 8; stbase = NQTOK; }

    if (tid == 0) s_cnt = 0;

    const int tok = tokbase + wid;
    float4 v = ((const float4*)in)[tok * 32 + lane];
    float ss = v.x*v.x + v.y*v.y + v.z*v.z + v.w*v.w;
    #pragma unroll
    for (int o = 16; o; o >>= 1) ss += __shfl_xor_sync(0xffffffffu, ss, o);
    float scale = 1.0f / fmaxf(sqrtf(ss), 1e-12f);
    v.x *= scale; v.y *= scale; v.z *= scale; v.w *= scale;

    red[wid * 128 + lane * 4 + 0] = v.x;
    red[wid * 128 + lane * 4 + 1] = v.y;
    red[wid * 128 + lane * 4 + 2] = v.z;
    red[wid * 128 + lane * 4 + 3] = v.w;

    const int m = mask[tok];
    if (m) {
        float4 t;
        t.x = f2tf32(v.x); t.y = f2tf32(v.y); t.z = f2tf32(v.z); t.w = f2tf32(v.w);
        ((float4*)(g_stage + (size_t)(stbase + tok) * H))[lane] = t;
    }

    __syncthreads();                 // red + s_cnt init visible
    if (lane == 0) atomicAdd(&s_cnt, m);
    __syncthreads();

    if (tid < 128) {
        float s = 0.f;
        #pragma unroll
        for (int w = 0; w < 8; w++) s += red[w * 128 + tid];
        atomicAdd(&sums[(tokbase / tpb) * 128 + tid], s);
    }
    if (tid == 0) atomicAdd(&cnt[tokbase / tpb], s_cnt);
}

// ---------------------------------------------------------------------------
// Kernel 2: offsets (q pad 8, d pad 32), tile counts, group->batch lookups.
// ---------------------------------------------------------------------------
__global__ void offsets_kernel()
{
    __shared__ int qoffs[NB], doffs[NB];
    int tid = threadIdx.x;   // 64
    if (tid == 0) {
        int acc = 0;
        for (int b = 0; b < NB; b++) { qoffs[b] = acc; acc += (G.qcnt[b] + 7) & ~7; }
        G.nqt = (acc + 127) >> 7;
        acc = 0;
        for (int b = 0; b < NB; b++) { doffs[b] = acc; acc += (G.dcnt[b] + 31) & ~31; }
        G.ndt = (acc + 127) >> 7;
    }
    __syncthreads();
    int b = tid;
    G.qoff[b] = qoffs[b];
    G.doff[b] = doffs[b];
    int qg0 = qoffs[b] >> 3, qg1 = (qoffs[b] + ((G.qcnt[b] + 7) & ~7)) >> 3;
    for (int gI = qg0; gI < qg1; gI++) G.qlk[gI] = b;
    int dg0 = doffs[b] >> 5, dg1 = (doffs[b] + ((G.dcnt[b] + 31) & ~31)) >> 5;
    for (int gI = dg0; gI < dg1; gI++) G.dlk[gI] = b;
}

// ---------------------------------------------------------------------------
// Kernel 3: scatter unmasked tokens from g_stage into compacted arrays.
// One warp per token (mask is warp-uniform).
// ---------------------------------------------------------------------------
__global__ void scatter_kernel(const int* __restrict__ qm, const int* __restrict__ dm)
{
    const int blk  = blockIdx.x;
    const int tid  = threadIdx.x;
    const int wid  = tid >> 5;
    const int lane = tid & 31;

    const int* mask; float* dstarr; int* cur; const int* off; int tpb, tokbase, stbase;
    if (blk < 256) { mask = qm; dstarr = G.qt; cur = G.qcur; off = G.qoff; tpb = SQ; tokbase = blk * 8; stbase = 0; }
    else           { mask = dm; dstarr = G.dt; cur = G.dcur; off = G.doff; tpb = SD; tokbase = (blk - 256) * 8; stbase = NQTOK; }

    const int tok = tokbase + wid;
    if (!mask[tok]) return;
    const int b = tokbase / tpb;
    int slot = 0;
    if (lane == 0) slot = atomicAdd(&cur[b], 1);
    slot = __shfl_sync(0xffffffffu, slot, 0);
    const int dst = off[b] + slot;
    ((float4*)(dstarr + (size_t)dst * H))[lane] =
        ((const float4*)(g_stage + (size_t)(stbase + tok) * H))[lane];
}

// ---------------------------------------------------------------------------
// Kernel 4: compacted tf32 max-GEMM + fused final loss.
// Fixed grid (128, 16) = worst case tiles; CTA (tj, ti) computes the
// 128x128 tile (q rows ti*128.., d rows tj*128..) if active, else skips.
// K split in 2 halves, double-buffered. 8 warps, 64x32 warp tiles.
// Epilogue: per (8-row group, 32-col group) max -> atomicMax scores[a][b].
// ---------------------------------------------------------------------------
#define KSTRIDE 68
#define HBUF (128 * KSTRIDE)            // floats per half-K buffer
#define SMEM_BYTES (4 * HBUF * 4)       // 139264 B

__device__ __forceinline__ void cp_half(uint32_t dst_u32, const float* __restrict__ src,
                                        int kh, int tid)
{
    #pragma unroll
    for (int i = 0; i < 8; i++) {
        int id  = i * 256 + tid;       // 2048 chunks: 128 rows x 16
        int row = id >> 4;
        int ck  = id & 15;
        CP_ASYNC16(dst_u32 + (row * KSTRIDE + ck * 4) * 4, src + row * H + kh * 64 + ck * 4);
    }
}

__global__ __launch_bounds__(256, 1) void maxgemm_kernel(float* __restrict__ out)
{
    extern __shared__ float sm[];
    __shared__ bool  s_last;
    __shared__ float s_avgq[64], s_avgd[64], s_red[64];

    const int tj   = blockIdx.x;     // d tile 0..127
    const int ti   = blockIdx.y;     // q tile 0..15
    const int tid  = threadIdx.x;    // 256
    const int wid  = tid >> 5;
    const int lane = tid & 31;
    const int g    = lane >> 2;
    const int tg   = lane & 3;
    const int wm   = wid >> 2;       // 0..1 -> 64 q rows
    const int wn   = wid & 3;        // 0..3 -> 32 d cols

    if (ti < G.nqt && tj < G.ndt) {
        float* sQ0 = sm;
        float* sQ1 = sm + HBUF;
        float* sD0 = sm + 2 * HBUF;
        float* sD1 = sm + 3 * HBUF;
        const float* qsrc = G.qt + (size_t)ti * 128 * H;
        const float* dsrc = G.dt + (size_t)tj * 128 * H;

        cp_half(smem_u32(sQ0), qsrc, 0, tid);
        cp_half(smem_u32(sD0), dsrc, 0, tid);
        CP_COMMIT();
        cp_half(smem_u32(sQ1), qsrc, 1, tid);
        cp_half(smem_u32(sD1), dsrc, 1, tid);
        CP_COMMIT();
        CP_WAIT1();
        __syncthreads();

        float acc[4][4][4];
        #pragma unroll
        for (int mt = 0; mt < 4; mt++)
            #pragma unroll
            for (int nb = 0; nb < 4; nb++)
                #pragma unroll
                for (int r = 0; r < 4; r++) acc[mt][nb][r] = 0.f;

        #pragma unroll
        for (int kh = 0; kh < 2; kh++) {
            const uint32_t* uQ = (const uint32_t*)(kh ? sQ1 : sQ0);
            const uint32_t* uD = (const uint32_t*)(kh ? sD1 : sD0);
            #pragma unroll
            for (int ks = 0; ks < 8; ks++) {
                const int k0 = 8 * ks + tg;
                uint32_t A[4][4];
                #pragma unroll
                for (int mt = 0; mt < 4; mt++) {
                    int r0 = (wm * 64 + mt * 16 + g) * KSTRIDE;
                    A[mt][0] = uQ[r0 + k0];
                    A[mt][1] = uQ[r0 + 8 * KSTRIDE + k0];
                    A[mt][2] = uQ[r0 + k0 + 4];
                    A[mt][3] = uQ[r0 + 8 * KSTRIDE + k0 + 4];
                }
                uint32_t B[4][2];
                #pragma unroll
                for (int nb = 0; nb < 4; nb++) {
                    int c0 = (wn * 32 + nb * 8 + g) * KSTRIDE;
                    B[nb][0] = uD[c0 + k0];
                    B[nb][1] = uD[c0 + k0 + 4];
                }
                #pragma unroll
                for (int mt = 0; mt < 4; mt++)
                    #pragma unroll
                    for (int nb = 0; nb < 4; nb++)
                        mma_tf32(acc[mt][nb][0], acc[mt][nb][1], acc[mt][nb][2], acc[mt][nb][3],
                                 A[mt][0], A[mt][1], A[mt][2], A[mt][3],
                                 B[nb][0], B[nb][1]);
            }
            if (kh == 0) { CP_WAIT0(); __syncthreads(); }
        }

        // ---- epilogue: per (8-row group, 32-col group) max -> atomicMax ----
        const int b = G.dlk[tj * 4 + wn];
        #pragma unroll
        for (int mt = 0; mt < 4; mt++) {
            float v0 = -1e30f, v1 = -1e30f;   // rows g (group+0) / g+8 (group+1)
            #pragma unroll
            for (int nb = 0; nb < 4; nb++) {
                v0 = fmaxf(v0, fmaxf(acc[mt][nb][0], acc[mt][nb][1]));
                v1 = fmaxf(v1, fmaxf(acc[mt][nb][2], acc[mt][nb][3]));
            }
            #pragma unroll
            for (int o = 16; o; o >>= 1) {
                v0 = fmaxf(v0, __shfl_xor_sync(0xffffffffu, v0, o));
                v1 = fmaxf(v1, __shfl_xor_sync(0xffffffffu, v1, o));
            }
            if (lane == 0) {
                int gbase = ti * 16 + wm * 8 + mt * 2;
                if (v0 > 0.f) {
                    int a0 = G.qlk[gbase];
                    atomicMax((int*)&G.scores[a0 * NB + b], __float_as_int(v0));
                }
                if (v1 > 0.f) {
                    int a1 = G.qlk[gbase + 1];
                    atomicMax((int*)&G.scores[a1 * NB + b], __float_as_int(v1));
                }
            }
        }
    }

    // ---- last-CTA fused final reduction (all 2048 CTAs count) ----
    __threadfence();
    __syncthreads();
    if (tid == 0) s_last = (atomicAdd(&G.done, 1u) == 2047u);
    __syncthreads();
    if (!s_last) return;
    if (tid == 0) G.done = 0;

    for (int b = wid; b < NB; b += 8) {
        float4 vq = ((const float4*)G.sumq)[b * 32 + lane];
        float4 vd = ((const float4*)G.sumd)[b * 32 + lane];
        float sq = vq.x*vq.x + vq.y*vq.y + vq.z*vq.z + vq.w*vq.w;
        float sd = vd.x*vd.x + vd.y*vd.y + vd.z*vd.z + vd.w*vd.w;
        #pragma unroll
        for (int o = 16; o; o >>= 1) {
            sq += __shfl_xor_sync(0xffffffffu, sq, o);
            sd += __shfl_xor_sync(0xffffffffu, sd, o);
        }
        if (lane == 0) {
            s_avgq[b] = (sq - (float)SQ) * (1.0f / ((float)SQ * (SQ - 1)));
            s_avgd[b] = (sd - (float)SD) * (1.0f / ((float)SD * (SD - 1)));
        }
    }
    __syncthreads();

    #pragma unroll
    for (int r = 0; r < 8; r++) {
        int a = wid * 8 + r;
        float v0 = __ldcg(&G.scores[a * NB + lane]);
        float v1 = __ldcg(&G.scores[a * NB + 32 + lane]);
        float mx = fmaxf(v0, v1);
        #pragma unroll
        for (int o = 16; o; o >>= 1) mx = fmaxf(mx, __shfl_xor_sync(0xffffffffu, mx, o));
        float sum = expf(v0 - mx) + expf(v1 - mx);
        #pragma unroll
        for (int o = 16; o; o >>= 1) sum += __shfl_xor_sync(0xffffffffu, sum, o);
        if (lane == 0) {
            float diag = __ldcg(&G.scores[a * NB + a]);
            s_red[a] = mx + logf(sum) - diag + s_avgq[a] + s_avgd[a];
        }
    }
    __syncthreads();
    if (tid < 32) {
        float v = s_red[tid] + s_red[tid + 32];
        #pragma unroll
        for (int o = 16; o; o >>= 1) v += __shfl_xor_sync(0xffffffffu, v, o);
        if (tid == 0) out[0] = v * (1.0f / NB);
    }
}

// ---------------------------------------------------------------------------
extern "C" void kernel_launch(void* const* d_in, const int* in_sizes, int n_in,
                              void* d_out, int out_size)
{
    const float* q_emb  = (const float*)d_in[0];
    const float* d_emb  = (const float*)d_in[1];
    const int*   q_mask = (const int*)  d_in[2];
    const int*   d_mask = (const int*)  d_in[3];
    float*       out    = (float*)d_out;

    cudaFuncSetAttribute(maxgemm_kernel,
                         cudaFuncAttributeMaxDynamicSharedMemorySize, SMEM_BYTES);

    void* gptr;
    cudaGetSymbolAddress(&gptr, G);
    cudaMemsetAsync(gptr, 0, sizeof(Scratch));

    norm_count<<<256 + 2048, 256>>>(q_emb, d_emb, q_mask, d_mask);
    offsets_kernel<<<1, 64>>>();
    scatter_kernel<<<256 + 2048, 256>>>(q_mask, d_mask);
    maxgemm_kernel<<<dim3(128, 16), 256, SMEM_BYTES>>>(out);
}

// round 10
// speedup vs baseline: 3.4295x; 1.1506x over previous
#include <cuda_runtime.h>
#include <math.h>
#include <stdint.h>

#define H    128
#define NB   64
#define SQ   32
#define SD   256
#define NQTOK (NB*SQ)   // 2048
#define NDTOK (NB*SD)   // 16384
#define QLK_N (NQTOK/8)    // 256 max 8-row groups
#define DLK_N (NDTOK/32)   // 512 max 32-col groups
#define NCTA 148

// ---------------- scratch (single struct -> one memset) ----------------
struct Scratch {
    float qt[NQTOK*H];      // compacted q (tf32, masked); padding stays zero
    float dt[NDTOK*H];      // compacted d
    float sumq[NB*H];
    float sumd[NB*H];
    float scores[NB*NB];    // atomicMax (int view), init 0 = mask floor
    int qcnt[NB], dcnt[NB];
    int qcur[NB], dcur[NB];
    int qlk[QLK_N];         // 8-row group -> batch a
    int dlk[DLK_N];         // 32-col group -> batch b
    int qoff[NB], doff[NB];
    int nqt, ndt;           // active tile counts
    unsigned done;
};
__device__ Scratch G;

// ---------------- helpers ----------------
__device__ __forceinline__ uint32_t smem_u32(const void* p) {
    uint32_t a;
    asm("{ .reg .u64 t; cvta.to.shared.u64 t, %1; cvt.u32.u64 %0, t; }" : "=r"(a) : "l"(p));
    return a;
}
__device__ __forceinline__ float f2tf32(float x) {
    uint32_t r;
    asm("cvt.rna.tf32.f32 %0, %1;" : "=r"(r) : "f"(x));
    return __uint_as_float(r);
}
__device__ __forceinline__ void mma_tf32(float& d0, float& d1, float& d2, float& d3,
                                         uint32_t a0, uint32_t a1, uint32_t a2, uint32_t a3,
                                         uint32_t b0, uint32_t b1) {
    asm volatile("mma.sync.aligned.m16n8k8.row.col.f32.tf32.tf32.f32 "
                 "{%0,%1,%2,%3}, {%4,%5,%6,%7}, {%8,%9}, {%0,%1,%2,%3};"
                 : "+f"(d0), "+f"(d1), "+f"(d2), "+f"(d3)
                 : "r"(a0), "r"(a1), "r"(a2), "r"(a3), "r"(b0), "r"(b1));
}
#define CP_ASYNC16(dst, src) \
    asm volatile("cp.async.cg.shared.global [%0], [%1], 16;" :: "r"(dst), "l"(src))
#define CP_COMMIT() asm volatile("cp.async.commit_group;" ::: "memory")
#define CP_WAIT0()  asm volatile("cp.async.wait_group 0;" ::: "memory")

// ---------------------------------------------------------------------------
// Kernel 1: mask counts + offsets + group->batch lookups. Single block.
// ---------------------------------------------------------------------------
__global__ void count_kernel(const int* __restrict__ qm, const int* __restrict__ dm)
{
    __shared__ int qc[NB], dc[NB];
    __shared__ int qoffs[NB], doffs[NB];
    const int tid = threadIdx.x;   // 1024

    if (tid < NB) { qc[tid] = 0; dc[tid] = 0; }
    __syncthreads();
    for (int i = tid; i < NQTOK; i += 1024) if (qm[i]) atomicAdd(&qc[i >> 5], 1);
    for (int i = tid; i < NDTOK; i += 1024) if (dm[i]) atomicAdd(&dc[i >> 8], 1);
    __syncthreads();

    if (tid == 0) {
        int acc = 0;
        for (int b = 0; b < NB; b++) { qoffs[b] = acc; acc += (qc[b] + 7) & ~7; }
        G.nqt = (acc + 127) >> 7;
        acc = 0;
        for (int b = 0; b < NB; b++) { doffs[b] = acc; acc += (dc[b] + 31) & ~31; }
        G.ndt = (acc + 127) >> 7;
    }
    __syncthreads();

    if (tid < NB) {
        int b = tid;
        G.qcnt[b] = qc[b];  G.dcnt[b] = dc[b];
        G.qoff[b] = qoffs[b];  G.doff[b] = doffs[b];
        int qg0 = qoffs[b] >> 3, qg1 = (qoffs[b] + ((qc[b] + 7) & ~7)) >> 3;
        for (int gI = qg0; gI < qg1; gI++) G.qlk[gI] = b;
        int dg0 = doffs[b] >> 5, dg1 = (doffs[b] + ((dc[b] + 31) & ~31)) >> 5;
        for (int gI = dg0; gI < dg1; gI++) G.dlk[gI] = b;
    }
}

// ---------------------------------------------------------------------------
// Kernel 2: normalize + per-batch sums + direct compacted scatter (tf32).
// blocks [0,256) = q tokens, [256,2304) = d. 8 tokens (one batch) per block.
// ---------------------------------------------------------------------------
__global__ void normscatter(const float* __restrict__ qin, const float* __restrict__ din,
                            const int* __restrict__ qm, const int* __restrict__ dm)
{
    __shared__ float red[8 * 128];
    const int blk  = blockIdx.x;
    const int tid  = threadIdx.x;
    const int wid  = tid >> 5;
    const int lane = tid & 31;

    const float* in; const int* mask; float* sums; float* dstarr; int* cur; const int* off;
    int tpb, tokbase;
    if (blk < 256) { in = qin; mask = qm; sums = G.sumq; dstarr = G.qt; cur = G.qcur; off = G.qoff; tpb = SQ; tokbase = blk * 8; }
    else           { in = din; mask = dm; sums = G.sumd; dstarr = G.dt; cur = G.dcur; off = G.doff; tpb = SD; tokbase = (blk - 256) * 8; }

    const int tok = tokbase + wid;
    const int b   = tokbase / tpb;
    float4 v = ((const float4*)in)[tok * 32 + lane];
    float ss = v.x*v.x + v.y*v.y + v.z*v.z + v.w*v.w;
    #pragma unroll
    for (int o = 16; o; o >>= 1) ss += __shfl_xor_sync(0xffffffffu, ss, o);
    float scale = 1.0f / fmaxf(sqrtf(ss), 1e-12f);
    v.x *= scale; v.y *= scale; v.z *= scale; v.w *= scale;

    red[wid * 128 + lane * 4 + 0] = v.x;
    red[wid * 128 + lane * 4 + 1] = v.y;
    red[wid * 128 + lane * 4 + 2] = v.z;
    red[wid * 128 + lane * 4 + 3] = v.w;

    if (mask[tok]) {
        int slot = 0;
        if (lane == 0) slot = atomicAdd(&cur[b], 1);
        slot = __shfl_sync(0xffffffffu, slot, 0);
        float4 t;
        t.x = f2tf32(v.x); t.y = f2tf32(v.y); t.z = f2tf32(v.z); t.w = f2tf32(v.w);
        ((float4*)(dstarr + (size_t)(off[b] + slot) * H))[lane] = t;
    }

    __syncthreads();
    if (tid < 128) {
        float s = 0.f;
        #pragma unroll
        for (int w = 0; w < 8; w++) s += red[w * 128 + tid];
        atomicAdd(&sums[b * 128 + tid], s);
    }
}

// ---------------------------------------------------------------------------
// Kernel 3: persistent compacted tf32 max-GEMM + fused final loss.
// Grid = 148 CTAs. CTA c: ti = c % nqt (Q resident, full K),
// tj = c/nqt + k*(148/nqt) (D double-buffered prefetch).
// 8 warps, 64x32 warp tiles, m16n8k8 tf32, stride-132 SMEM.
// Epilogue: per (8-row, 32-col) group max -> atomicMax(scores[a][b]) if > 0.
// ---------------------------------------------------------------------------
#define STRIDE 132
#define TILE_FLOATS (128 * STRIDE)
#define SMEM_BYTES (3 * TILE_FLOATS * 4)   // 202752 B

__device__ __forceinline__ void cp_tile(float* dst, const float* __restrict__ src, int tid)
{
    #pragma unroll
    for (int i = 0; i < 16; i++) {
        int id  = i * 256 + tid;       // 4096 chunks: 128 rows x 32
        int row = id >> 5;
        int ck  = id & 31;
        CP_ASYNC16(smem_u32(dst + row * STRIDE + ck * 4), src + row * H + ck * 4);
    }
}

__global__ __launch_bounds__(256, 1) void maxgemm_kernel(float* __restrict__ out)
{
    extern __shared__ float sm[];
    float* sQ  = sm;
    float* sD0 = sm + TILE_FLOATS;
    float* sD1 = sm + 2 * TILE_FLOATS;

    __shared__ bool  s_last;
    __shared__ float s_avgq[64], s_avgd[64], s_red[64];

    const int c    = blockIdx.x;     // 0..147
    const int tid  = threadIdx.x;    // 256
    const int wid  = tid >> 5;
    const int lane = tid & 31;
    const int g    = lane >> 2;
    const int tg   = lane & 3;
    const int wm   = wid >> 2;       // 0..1 -> 64 q rows
    const int wn   = wid & 3;        // 0..3 -> 32 d cols

    const int nqt = G.nqt;
    const int ndt = G.ndt;
    const int P   = (nqt > 0) ? (NCTA / nqt) : 0;   // CTAs per q-tile

    if (nqt > 0 && c < nqt * P) {
        const int ti = c % nqt;
        const int j0 = c / nqt;

        cp_tile(sQ, G.qt + (size_t)ti * 128 * H, tid);
        if (j0 < ndt) cp_tile(sD0, G.dt + (size_t)j0 * 128 * H, tid);
        CP_COMMIT();
        CP_WAIT0();
        __syncthreads();

        const uint32_t* uQ = (const uint32_t*)sQ;

        for (int tj = j0; tj < ndt; tj += P) {
            float* curD = ((tj - j0) / P & 1) ? sD1 : sD0;
            float* nxtD = ((tj - j0) / P & 1) ? sD0 : sD1;
            if (tj + P < ndt) {
                cp_tile(nxtD, G.dt + (size_t)(tj + P) * 128 * H, tid);
                CP_COMMIT();
            }
            const uint32_t* uD = (const uint32_t*)curD;

            float acc[4][4][4];
            #pragma unroll
            for (int mt = 0; mt < 4; mt++)
                #pragma unroll
                for (int nb = 0; nb < 4; nb++)
                    #pragma unroll
                    for (int r = 0; r < 4; r++) acc[mt][nb][r] = 0.f;

            #pragma unroll
            for (int ks = 0; ks < 16; ks++) {
                const int k0 = 8 * ks + tg;
                uint32_t A[4][4];
                #pragma unroll
                for (int mt = 0; mt < 4; mt++) {
                    int r0 = (wm * 64 + mt * 16 + g) * STRIDE;
                    A[mt][0] = uQ[r0 + k0];
                    A[mt][1] = uQ[r0 + 8 * STRIDE + k0];
                    A[mt][2] = uQ[r0 + k0 + 4];
                    A[mt][3] = uQ[r0 + 8 * STRIDE + k0 + 4];
                }
                uint32_t B[4][2];
                #pragma unroll
                for (int nb = 0; nb < 4; nb++) {
                    int c0 = (wn * 32 + nb * 8 + g) * STRIDE;
                    B[nb][0] = uD[c0 + k0];
                    B[nb][1] = uD[c0 + k0 + 4];
                }
                #pragma unroll
                for (int mt = 0; mt < 4; mt++)
                    #pragma unroll
                    for (int nb = 0; nb < 4; nb++)
                        mma_tf32(acc[mt][nb][0], acc[mt][nb][1], acc[mt][nb][2], acc[mt][nb][3],
                                 A[mt][0], A[mt][1], A[mt][2], A[mt][3],
                                 B[nb][0], B[nb][1]);
            }

            // ---- epilogue: (8-row group, 32-col group) max -> atomicMax ----
            const int b = G.dlk[tj * 4 + wn];
            #pragma unroll
            for (int mt = 0; mt < 4; mt++) {
                float v0 = -1e30f, v1 = -1e30f;   // row groups mt*2 / mt*2+1
                #pragma unroll
                for (int nb = 0; nb < 4; nb++) {
                    v0 = fmaxf(v0, fmaxf(acc[mt][nb][0], acc[mt][nb][1]));
                    v1 = fmaxf(v1, fmaxf(acc[mt][nb][2], acc[mt][nb][3]));
                }
                #pragma unroll
                for (int o = 16; o; o >>= 1) {
                    v0 = fmaxf(v0, __shfl_xor_sync(0xffffffffu, v0, o));
                    v1 = fmaxf(v1, __shfl_xor_sync(0xffffffffu, v1, o));
                }
                if (lane == 0) {
                    int gbase = ti * 16 + wm * 8 + mt * 2;
                    if (v0 > 0.f)
                        atomicMax((int*)&G.scores[G.qlk[gbase] * NB + b], __float_as_int(v0));
                    if (v1 > 0.f)
                        atomicMax((int*)&G.scores[G.qlk[gbase + 1] * NB + b], __float_as_int(v1));
                }
            }

            CP_WAIT0();
            __syncthreads();
        }
    }

    // ---- last-CTA fused final reduction ----
    __threadfence();
    __syncthreads();
    if (tid == 0) s_last = (atomicAdd(&G.done, 1u) == NCTA - 1u);
    __syncthreads();
    if (!s_last) return;
    if (tid == 0) G.done = 0;

    for (int b = wid; b < NB; b += 8) {
        float4 vq = ((const float4*)G.sumq)[b * 32 + lane];
        float4 vd = ((const float4*)G.sumd)[b * 32 + lane];
        float sq = vq.x*vq.x + vq.y*vq.y + vq.z*vq.z + vq.w*vq.w;
        float sd = vd.x*vd.x + vd.y*vd.y + vd.z*vd.z + vd.w*vd.w;
        #pragma unroll
        for (int o = 16; o; o >>= 1) {
            sq += __shfl_xor_sync(0xffffffffu, sq, o);
            sd += __shfl_xor_sync(0xffffffffu, sd, o);
        }
        if (lane == 0) {
            s_avgq[b] = (sq - (float)SQ) * (1.0f / ((float)SQ * (SQ - 1)));
            s_avgd[b] = (sd - (float)SD) * (1.0f / ((float)SD * (SD - 1)));
        }
    }
    __syncthreads();

    #pragma unroll
    for (int r = 0; r < 8; r++) {
        int a = wid * 8 + r;
        float v0 = __ldcg(&G.scores[a * NB + lane]);
        float v1 = __ldcg(&G.scores[a * NB + 32 + lane]);
        float mx = fmaxf(v0, v1);
        #pragma unroll
        for (int o = 16; o; o >>= 1) mx = fmaxf(mx, __shfl_xor_sync(0xffffffffu, mx, o));
        float sum = expf(v0 - mx) + expf(v1 - mx);
        #pragma unroll
        for (int o = 16; o; o >>= 1) sum += __shfl_xor_sync(0xffffffffu, sum, o);
        if (lane == 0) {
            float diag = __ldcg(&G.scores[a * NB + a]);
            s_red[a] = mx + logf(sum) - diag + s_avgq[a] + s_avgd[a];
        }
    }
    __syncthreads();
    if (tid < 32) {
        float v = s_red[tid] + s_red[tid + 32];
        #pragma unroll
        for (int o = 16; o; o >>= 1) v += __shfl_xor_sync(0xffffffffu, v, o);
        if (tid == 0) out[0] = v * (1.0f / NB);
    }
}

// ---------------------------------------------------------------------------
extern "C" void kernel_launch(void* const* d_in, const int* in_sizes, int n_in,
                              void* d_out, int out_size)
{
    const float* q_emb  = (const float*)d_in[0];
    const float* d_emb  = (const float*)d_in[1];
    const int*   q_mask = (const int*)  d_in[2];
    const int*   d_mask = (const int*)  d_in[3];
    float*       out    = (float*)d_out;

    cudaFuncSetAttribute(maxgemm_kernel,
                         cudaFuncAttributeMaxDynamicSharedMemorySize, SMEM_BYTES);

    void* gptr;
    cudaGetSymbolAddress(&gptr, G);
    cudaMemsetAsync(gptr, 0, sizeof(Scratch));

    count_kernel<<<1, 1024>>>(q_mask, d_mask);
    normscatter<<<256 + 2048, 256>>>(q_emb, d_emb, q_mask, d_mask);
    maxgemm_kernel<<<NCTA, 256, SMEM_BYTES>>>(out);
}

// round 11
// speedup vs baseline: 3.5424x; 1.0329x over previous
#include <cuda_runtime.h>
#include <math.h>
#include <stdint.h>

#define H    128
#define NB   64
#define SQ   32
#define SD   256
#define NQTOK (NB*SQ)   // 2048
#define NDTOK (NB*SD)   // 16384
#define QLK_N (NQTOK/8)    // 256 max 8-row groups
#define DLK_N (NDTOK/32)   // 512 max 32-col groups
#define NCTA 148

// ---------------- scratch (single struct -> one memset) ----------------
struct Scratch {
    float qt[NQTOK*H];      // compacted q (tf32, masked); padding stays zero
    float dt[NDTOK*H];      // compacted d
    float sumq[NB*H];
    float sumd[NB*H];
    float scores[NB*NB];    // atomicMax (int view), init 0 = mask floor
    int qcnt[NB], dcnt[NB];
    int qcur[NB], dcur[NB];
    int qlk[QLK_N];         // 8-row group -> batch a
    int dlk[DLK_N];         // 32-col group -> batch b
    int qoff[NB], doff[NB];
    int nqt, ndt;           // active tile counts
    unsigned done;
};
__device__ Scratch G;

// ---------------- helpers ----------------
__device__ __forceinline__ uint32_t smem_u32(const void* p) {
    uint32_t a;
    asm("{ .reg .u64 t; cvta.to.shared.u64 t, %1; cvt.u32.u64 %0, t; }" : "=r"(a) : "l"(p));
    return a;
}
__device__ __forceinline__ float f2tf32(float x) {
    uint32_t r;
    asm("cvt.rna.tf32.f32 %0, %1;" : "=r"(r) : "f"(x));
    return __uint_as_float(r);
}
__device__ __forceinline__ void mma_tf32(float& d0, float& d1, float& d2, float& d3,
                                         uint32_t a0, uint32_t a1, uint32_t a2, uint32_t a3,
                                         uint32_t b0, uint32_t b1) {
    asm volatile("mma.sync.aligned.m16n8k8.row.col.f32.tf32.tf32.f32 "
                 "{%0,%1,%2,%3}, {%4,%5,%6,%7}, {%8,%9}, {%0,%1,%2,%3};"
                 : "+f"(d0), "+f"(d1), "+f"(d2), "+f"(d3)
                 : "r"(a0), "r"(a1), "r"(a2), "r"(a3), "r"(b0), "r"(b1));
}
#define CP_ASYNC16(dst, src) \
    asm volatile("cp.async.cg.shared.global [%0], [%1], 16;" :: "r"(dst), "l"(src))
#define CP_COMMIT() asm volatile("cp.async.commit_group;" ::: "memory")
#define CP_WAIT0()  asm volatile("cp.async.wait_group 0;" ::: "memory")

// ---------------------------------------------------------------------------
// Kernel 1: mask counts (ballot+popc: 1 atomic/warp) + offsets + lookups.
// Single block, 1024 threads.
// ---------------------------------------------------------------------------
__global__ void count_kernel(const int* __restrict__ qm, const int* __restrict__ dm)
{
    __shared__ int qc[NB], dc[NB];
    __shared__ int qoffs[NB], doffs[NB];
    const int tid  = threadIdx.x;   // 1024
    const int lane = tid & 31;

    if (tid < NB) { qc[tid] = 0; dc[tid] = 0; }
    __syncthreads();
    // warp spans 32 consecutive tokens -> batch index uniform per warp
    #pragma unroll 2
    for (int i = tid; i < NQTOK; i += 1024) {
        unsigned bal = __ballot_sync(0xffffffffu, qm[i] != 0);
        if (lane == 0) atomicAdd(&qc[i >> 5], __popc(bal));
    }
    #pragma unroll 4
    for (int i = tid; i < NDTOK; i += 1024) {
        unsigned bal = __ballot_sync(0xffffffffu, dm[i] != 0);
        if (lane == 0) atomicAdd(&dc[i >> 8], __popc(bal));
    }
    __syncthreads();

    if (tid == 0) {
        int acc = 0;
        for (int b = 0; b < NB; b++) { qoffs[b] = acc; acc += (qc[b] + 7) & ~7; }
        G.nqt = (acc + 127) >> 7;
        acc = 0;
        for (int b = 0; b < NB; b++) { doffs[b] = acc; acc += (dc[b] + 31) & ~31; }
        G.ndt = (acc + 127) >> 7;
    }
    __syncthreads();

    if (tid < NB) {
        int b = tid;
        G.qcnt[b] = qc[b];  G.dcnt[b] = dc[b];
        G.qoff[b] = qoffs[b];  G.doff[b] = doffs[b];
        int qg0 = qoffs[b] >> 3, qg1 = (qoffs[b] + ((qc[b] + 7) & ~7)) >> 3;
        for (int gI = qg0; gI < qg1; gI++) G.qlk[gI] = b;
        int dg0 = doffs[b] >> 5, dg1 = (doffs[b] + ((dc[b] + 31) & ~31)) >> 5;
        for (int gI = dg0; gI < dg1; gI++) G.dlk[gI] = b;
    }
}

// ---------------------------------------------------------------------------
// Kernel 2: normalize + per-batch sums + direct compacted scatter (tf32).
// blocks [0,256) = q tokens, [256,2304) = d. 8 tokens (one batch) per block.
// ---------------------------------------------------------------------------
__global__ void normscatter(const float* __restrict__ qin, const float* __restrict__ din,
                            const int* __restrict__ qm, const int* __restrict__ dm)
{
    __shared__ float red[8 * 128];
    const int blk  = blockIdx.x;
    const int tid  = threadIdx.x;
    const int wid  = tid >> 5;
    const int lane = tid & 31;

    const float* in; const int* mask; float* sums; float* dstarr; int* cur; const int* off;
    int tpb, tokbase;
    if (blk < 256) { in = qin; mask = qm; sums = G.sumq; dstarr = G.qt; cur = G.qcur; off = G.qoff; tpb = SQ; tokbase = blk * 8; }
    else           { in = din; mask = dm; sums = G.sumd; dstarr = G.dt; cur = G.dcur; off = G.doff; tpb = SD; tokbase = (blk - 256) * 8; }

    const int tok = tokbase + wid;
    const int b   = tokbase / tpb;
    float4 v = ((const float4*)in)[tok * 32 + lane];
    float ss = v.x*v.x + v.y*v.y + v.z*v.z + v.w*v.w;
    #pragma unroll
    for (int o = 16; o; o >>= 1) ss += __shfl_xor_sync(0xffffffffu, ss, o);
    float scale = 1.0f / fmaxf(sqrtf(ss), 1e-12f);
    v.x *= scale; v.y *= scale; v.z *= scale; v.w *= scale;

    red[wid * 128 + lane * 4 + 0] = v.x;
    red[wid * 128 + lane * 4 + 1] = v.y;
    red[wid * 128 + lane * 4 + 2] = v.z;
    red[wid * 128 + lane * 4 + 3] = v.w;

    if (mask[tok]) {
        int slot = 0;
        if (lane == 0) slot = atomicAdd(&cur[b], 1);
        slot = __shfl_sync(0xffffffffu, slot, 0);
        float4 t;
        t.x = f2tf32(v.x); t.y = f2tf32(v.y); t.z = f2tf32(v.z); t.w = f2tf32(v.w);
        ((float4*)(dstarr + (size_t)(off[b] + slot) * H))[lane] = t;
    }

    __syncthreads();
    if (tid < 128) {
        float s = 0.f;
        #pragma unroll
        for (int w = 0; w < 8; w++) s += red[w * 128 + tid];
        atomicAdd(&sums[b * 128 + tid], s);
    }
}

// ---------------------------------------------------------------------------
// Kernel 3: persistent compacted tf32 max-GEMM + fused final loss.
// 148 CTAs; flattened tile space idx = ti*ndt + tj split in equal chunks.
// Q reloads only on ti change within a chunk (rare). D double-buffered.
// 8 warps, 64x32 warp tiles, m16n8k8 tf32, stride-132 SMEM.
// Epilogue: per (8-row, 32-col) group max -> atomicMax(scores[a][b]) if > 0.
// ---------------------------------------------------------------------------
#define STRIDE 132
#define TILE_FLOATS (128 * STRIDE)
#define SMEM_BYTES (3 * TILE_FLOATS * 4)   // 202752 B

__device__ __forceinline__ void cp_tile(float* dst, const float* __restrict__ src, int tid)
{
    #pragma unroll
    for (int i = 0; i < 16; i++) {
        int id  = i * 256 + tid;       // 4096 chunks: 128 rows x 32
        int row = id >> 5;
        int ck  = id & 31;
        CP_ASYNC16(smem_u32(dst + row * STRIDE + ck * 4), src + row * H + ck * 4);
    }
}

__global__ __launch_bounds__(256, 1) void maxgemm_kernel(float* __restrict__ out)
{
    extern __shared__ float sm[];
    float* sQ  = sm;
    float* sD0 = sm + TILE_FLOATS;
    float* sD1 = sm + 2 * TILE_FLOATS;

    __shared__ bool  s_last;
    __shared__ float s_avgq[64], s_avgd[64], s_red[64];

    const int c    = blockIdx.x;     // 0..147
    const int tid  = threadIdx.x;    // 256
    const int wid  = tid >> 5;
    const int lane = tid & 31;
    const int g    = lane >> 2;
    const int tg   = lane & 3;
    const int wm   = wid >> 2;       // 0..1 -> 64 q rows
    const int wn   = wid & 3;        // 0..3 -> 32 d cols

    const int nqt = G.nqt;
    const int ndt = G.ndt;
    const int T   = nqt * ndt;
    const int chunk = (T + NCTA - 1) / NCTA;
    const int i0 = min(c * chunk, T);
    const int i1 = min(i0 + chunk, T);

    if (i0 < i1) {
        int ti_cur = i0 / ndt;
        cp_tile(sQ, G.qt + (size_t)ti_cur * 128 * H, tid);
        cp_tile(sD0, G.dt + (size_t)(i0 % ndt) * 128 * H, tid);
        CP_COMMIT();
        CP_WAIT0();
        __syncthreads();

        const uint32_t* uQ = (const uint32_t*)sQ;

        for (int idx = i0; idx < i1; idx++) {
            const int ti = idx / ndt;
            const int tj = idx % ndt;
            float* curD = ((idx - i0) & 1) ? sD1 : sD0;
            float* nxtD = ((idx - i0) & 1) ? sD0 : sD1;
            if (idx + 1 < i1)
                cp_tile(nxtD, G.dt + (size_t)((idx + 1) % ndt) * 128 * H, tid);
            const uint32_t* uD = (const uint32_t*)curD;

            float acc[4][4][4];
            #pragma unroll
            for (int mt = 0; mt < 4; mt++)
                #pragma unroll
                for (int nb = 0; nb < 4; nb++)
                    #pragma unroll
                    for (int r = 0; r < 4; r++) acc[mt][nb][r] = 0.f;

            #pragma unroll
            for (int ks = 0; ks < 16; ks++) {
                const int k0 = 8 * ks + tg;
                uint32_t A[4][4];
                #pragma unroll
                for (int mt = 0; mt < 4; mt++) {
                    int r0 = (wm * 64 + mt * 16 + g) * STRIDE;
                    A[mt][0] = uQ[r0 + k0];
                    A[mt][1] = uQ[r0 + 8 * STRIDE + k0];
                    A[mt][2] = uQ[r0 + k0 + 4];
                    A[mt][3] = uQ[r0 + 8 * STRIDE + k0 + 4];
                }
                uint32_t B[4][2];
                #pragma unroll
                for (int nb = 0; nb < 4; nb++) {
                    int c0 = (wn * 32 + nb * 8 + g) * STRIDE;
                    B[nb][0] = uD[c0 + k0];
                    B[nb][1] = uD[c0 + k0 + 4];
                }
                #pragma unroll
                for (int mt = 0; mt < 4; mt++)
                    #pragma unroll
                    for (int nb = 0; nb < 4; nb++)
                        mma_tf32(acc[mt][nb][0], acc[mt][nb][1], acc[mt][nb][2], acc[mt][nb][3],
                                 A[mt][0], A[mt][1], A[mt][2], A[mt][3],
                                 B[nb][0], B[nb][1]);
            }

            // ---- epilogue: (8-row group, 32-col group) max -> atomicMax ----
            const int b = G.dlk[tj * 4 + wn];
            #pragma unroll
            for (int mt = 0; mt < 4; mt++) {
                float v0 = -1e30f, v1 = -1e30f;
                #pragma unroll
                for (int nb = 0; nb < 4; nb++) {
                    v0 = fmaxf(v0, fmaxf(acc[mt][nb][0], acc[mt][nb][1]));
                    v1 = fmaxf(v1, fmaxf(acc[mt][nb][2], acc[mt][nb][3]));
                }
                #pragma unroll
                for (int o = 16; o; o >>= 1) {
                    v0 = fmaxf(v0, __shfl_xor_sync(0xffffffffu, v0, o));
                    v1 = fmaxf(v1, __shfl_xor_sync(0xffffffffu, v1, o));
                }
                if (lane == 0) {
                    int gbase = ti * 16 + wm * 8 + mt * 2;
                    if (v0 > 0.f)
                        atomicMax((int*)&G.scores[G.qlk[gbase] * NB + b], __float_as_int(v0));
                    if (v1 > 0.f)
                        atomicMax((int*)&G.scores[G.qlk[gbase + 1] * NB + b], __float_as_int(v1));
                }
            }

            // ---- prepare next iteration ----
            if (idx + 1 < i1) {
                int ti_n = (idx + 1) / ndt;
                if (ti_n != ti_cur) {
                    cp_tile(sQ, G.qt + (size_t)ti_n * 128 * H, tid);
                    ti_cur = ti_n;
                }
                CP_COMMIT();
                CP_WAIT0();
                __syncthreads();
            }
        }
    }

    // ---- last-CTA fused final reduction ----
    __threadfence();
    __syncthreads();
    if (tid == 0) s_last = (atomicAdd(&G.done, 1u) == NCTA - 1u);
    __syncthreads();
    if (!s_last) return;
    if (tid == 0) G.done = 0;

    for (int b = wid; b < NB; b += 8) {
        float4 vq = ((const float4*)G.sumq)[b * 32 + lane];
        float4 vd = ((const float4*)G.sumd)[b * 32 + lane];
        float sq = vq.x*vq.x + vq.y*vq.y + vq.z*vq.z + vq.w*vq.w;
        float sd = vd.x*vd.x + vd.y*vd.y + vd.z*vd.z + vd.w*vd.w;
        #pragma unroll
        for (int o = 16; o; o >>= 1) {
            sq += __shfl_xor_sync(0xffffffffu, sq, o);
            sd += __shfl_xor_sync(0xffffffffu, sd, o);
        }
        if (lane == 0) {
            s_avgq[b] = (sq - (float)SQ) * (1.0f / ((float)SQ * (SQ - 1)));
            s_avgd[b] = (sd - (float)SD) * (1.0f / ((float)SD * (SD - 1)));
        }
    }
    __syncthreads();

    #pragma unroll
    for (int r = 0; r < 8; r++) {
        int a = wid * 8 + r;
        float v0 = __ldcg(&G.scores[a * NB + lane]);
        float v1 = __ldcg(&G.scores[a * NB + 32 + lane]);
        float mx = fmaxf(v0, v1);
        #pragma unroll
        for (int o = 16; o; o >>= 1) mx = fmaxf(mx, __shfl_xor_sync(0xffffffffu, mx, o));
        float sum = expf(v0 - mx) + expf(v1 - mx);
        #pragma unroll
        for (int o = 16; o; o >>= 1) sum += __shfl_xor_sync(0xffffffffu, sum, o);
        if (lane == 0) {
            float diag = __ldcg(&G.scores[a * NB + a]);
            s_red[a] = mx + logf(sum) - diag + s_avgq[a] + s_avgd[a];
        }
    }
    __syncthreads();
    if (tid < 32) {
        float v = s_red[tid] + s_red[tid + 32];
        #pragma unroll
        for (int o = 16; o; o >>= 1) v += __shfl_xor_sync(0xffffffffu, v, o);
        if (tid == 0) out[0] = v * (1.0f / NB);
    }
}

// ---------------------------------------------------------------------------
extern "C" void kernel_launch(void* const* d_in, const int* in_sizes, int n_in,
                              void* d_out, int out_size)
{
    const float* q_emb  = (const float*)d_in[0];
    const float* d_emb  = (const float*)d_in[1];
    const int*   q_mask = (const int*)  d_in[2];
    const int*   d_mask = (const int*)  d_in[3];
    float*       out    = (float*)d_out;

    cudaFuncSetAttribute(maxgemm_kernel,
                         cudaFuncAttributeMaxDynamicSharedMemorySize, SMEM_BYTES);

    void* gptr;
    cudaGetSymbolAddress(&gptr, G);
    cudaMemsetAsync(gptr, 0, sizeof(Scratch));

    count_kernel<<<1, 1024>>>(q_mask, d_mask);
    normscatter<<<256 + 2048, 256>>>(q_emb, d_emb, q_mask, d_mask);
    maxgemm_kernel<<<NCTA, 256, SMEM_BYTES>>>(out);
}

// round 12
// speedup vs baseline: 3.7263x; 1.0519x over previous
#include <cuda_runtime.h>
#include <math.h>
#include <stdint.h>

#define H    128
#define NB   64
#define SQ   32
#define SD   256
#define NQTOK (NB*SQ)   // 2048
#define NDTOK (NB*SD)   // 16384
#define QLK_N (NQTOK/8)    // 256 max 8-row groups
#define DLK_N (NDTOK/32)   // 512 max 32-col groups
#define NCTA 148

// ---------------- scratch ----------------
// Zero-init at module load. qt/dt padding slots are never written (stay 0);
// scatter rewrites slots [0,cnt) fully every run -> no stale data.
// Non-idempotent accumulators (sumq..scores, qcur/dcur) are zeroed by
// count_kernel each run. done self-resets.
struct Scratch {
    float qt[NQTOK*H];      // compacted q (tf32, masked)
    float dt[NDTOK*H];      // compacted d
    float sumq[NB*H];       // | contiguous zero region:
    float sumd[NB*H];       // | 8192+8192+4096 floats
    float scores[NB*NB];    // | (atomicMax int view, 0 = mask floor)
    int qcur[NB], dcur[NB];
    int qlk[QLK_N];         // 8-row group -> batch a
    int dlk[DLK_N];         // 32-col group -> batch b
    int qoff[NB], doff[NB];
    int nqt, ndt;
    unsigned done;
};
__device__ Scratch G;

// ---------------- helpers ----------------
__device__ __forceinline__ uint32_t smem_u32(const void* p) {
    uint32_t a;
    asm("{ .reg .u64 t; cvta.to.shared.u64 t, %1; cvt.u32.u64 %0, t; }" : "=r"(a) : "l"(p));
    return a;
}
__device__ __forceinline__ float f2tf32(float x) {
    uint32_t r;
    asm("cvt.rna.tf32.f32 %0, %1;" : "=r"(r) : "f"(x));
    return __uint_as_float(r);
}
__device__ __forceinline__ void mma_tf32(float& d0, float& d1, float& d2, float& d3,
                                         uint32_t a0, uint32_t a1, uint32_t a2, uint32_t a3,
                                         uint32_t b0, uint32_t b1) {
    asm volatile("mma.sync.aligned.m16n8k8.row.col.f32.tf32.tf32.f32 "
                 "{%0,%1,%2,%3}, {%4,%5,%6,%7}, {%8,%9}, {%0,%1,%2,%3};"
                 : "+f"(d0), "+f"(d1), "+f"(d2), "+f"(d3)
                 : "r"(a0), "r"(a1), "r"(a2), "r"(a3), "r"(b0), "r"(b1));
}
#define CP_ASYNC16(dst, src) \
    asm volatile("cp.async.cg.shared.global [%0], [%1], 16;" :: "r"(dst), "l"(src))
#define CP_COMMIT() asm volatile("cp.async.commit_group;" ::: "memory")
#define CP_WAIT0()  asm volatile("cp.async.wait_group 0;" ::: "memory")

// ---------------------------------------------------------------------------
// Kernel 1: zero accumulators + mask counts (ballot) + shfl-scan offsets +
// group->batch lookups. Single block, 1024 threads. No serial chains.
// ---------------------------------------------------------------------------
__global__ void count_kernel(const int* __restrict__ qm, const int* __restrict__ dm)
{
    __shared__ int qc[NB], dc[NB];
    const int tid  = threadIdx.x;   // 1024
    const int lane = tid & 31;
    const int wrp  = tid >> 5;

    // zero the accumulator region (sumq, sumd, scores) + cursors
    float* zbase = G.sumq;
    #pragma unroll
    for (int i = tid; i < 2 * NB * H + NB * NB; i += 1024) zbase[i] = 0.f;
    if (tid < NB) { G.qcur[tid] = 0; G.dcur[tid] = 0; dc[tid] = 0; }
    __syncthreads();

    // q: each warp covers exactly one batch (32 tokens) per iter -> direct store
    #pragma unroll
    for (int it = 0; it < 2; it++) {
        int i = it * 1024 + tid;
        unsigned bal = __ballot_sync(0xffffffffu, qm[i] != 0);
        if (lane == 0) qc[i >> 5] = __popc(bal);
    }
    // d: 8 warps per batch -> atomicAdd (8 per address, cheap)
    #pragma unroll
    for (int it = 0; it < 16; it++) {
        int i = it * 1024 + tid;
        unsigned bal = __ballot_sync(0xffffffffu, dm[i] != 0);
        if (lane == 0) atomicAdd(&dc[i >> 8], __popc(bal));
    }
    __syncthreads();

    // warp 0: q scan (2 batches/lane, pad 8); warp 1: d scan (pad 32)
    if (wrp == 0) {
        int p0 = (qc[2 * lane] + 7) & ~7;
        int p1 = (qc[2 * lane + 1] + 7) & ~7;
        int s = p0 + p1, incl = s;
        #pragma unroll
        for (int o = 1; o < 32; o <<= 1) {
            int t = __shfl_up_sync(0xffffffffu, incl, o);
            if (lane >= o) incl += t;
        }
        int excl = incl - s;
        G.qoff[2 * lane]     = excl;
        G.qoff[2 * lane + 1] = excl + p0;
        int total = __shfl_sync(0xffffffffu, incl, 31);
        if (lane == 0) G.nqt = (total + 127) >> 7;
        for (int gI = excl >> 3; gI < (excl + p0) >> 3; gI++) G.qlk[gI] = 2 * lane;
        for (int gI = (excl + p0) >> 3; gI < (excl + p0 + p1) >> 3; gI++) G.qlk[gI] = 2 * lane + 1;
    } else if (wrp == 1) {
        int p0 = (dc[2 * lane] + 31) & ~31;
        int p1 = (dc[2 * lane + 1] + 31) & ~31;
        int s = p0 + p1, incl = s;
        #pragma unroll
        for (int o = 1; o < 32; o <<= 1) {
            int t = __shfl_up_sync(0xffffffffu, incl, o);
            if (lane >= o) incl += t;
        }
        int excl = incl - s;
        G.doff[2 * lane]     = excl;
        G.doff[2 * lane + 1] = excl + p0;
        int total = __shfl_sync(0xffffffffu, incl, 31);
        if (lane == 0) G.ndt = (total + 127) >> 7;
        for (int gI = excl >> 5; gI < (excl + p0) >> 5; gI++) G.dlk[gI] = 2 * lane;
        for (int gI = (excl + p0) >> 5; gI < (excl + p0 + p1) >> 5; gI++) G.dlk[gI] = 2 * lane + 1;
    }
}

// ---------------------------------------------------------------------------
// Kernel 2: normalize + per-batch sums + direct compacted scatter (tf32).
// 576 blocks x 256 thr; block = 32 tokens (one batch-uniform chunk),
// warp = 4 tokens. blocks [0,64) = q, [64,576) = d.
// ---------------------------------------------------------------------------
__global__ void normscatter(const float* __restrict__ qin, const float* __restrict__ din,
                            const int* __restrict__ qm, const int* __restrict__ dm)
{
    __shared__ float red[8 * 128];
    const int blk  = blockIdx.x;
    const int tid  = threadIdx.x;
    const int wid  = tid >> 5;
    const int lane = tid & 31;

    const float* in; const int* mask; float* sums; float* dstarr; int* cur; const int* off;
    int tokbase, b;
    if (blk < 64) { in = qin; mask = qm; sums = G.sumq; dstarr = G.qt; cur = G.qcur; off = G.qoff;
                    tokbase = blk * 32; b = blk; }
    else          { in = din; mask = dm; sums = G.sumd; dstarr = G.dt; cur = G.dcur; off = G.doff;
                    tokbase = (blk - 64) * 32; b = (blk - 64) >> 3; }

    float4 acc = make_float4(0.f, 0.f, 0.f, 0.f);
    #pragma unroll
    for (int j = 0; j < 4; j++) {
        const int tok = tokbase + wid * 4 + j;
        float4 v = ((const float4*)in)[tok * 32 + lane];
        float ss = v.x*v.x + v.y*v.y + v.z*v.z + v.w*v.w;
        #pragma unroll
        for (int o = 16; o; o >>= 1) ss += __shfl_xor_sync(0xffffffffu, ss, o);
        float scale = 1.0f / fmaxf(sqrtf(ss), 1e-12f);
        v.x *= scale; v.y *= scale; v.z *= scale; v.w *= scale;
        acc.x += v.x; acc.y += v.y; acc.z += v.z; acc.w += v.w;

        if (mask[tok]) {
            int slot = 0;
            if (lane == 0) slot = atomicAdd(&cur[b], 1);
            slot = __shfl_sync(0xffffffffu, slot, 0);
            float4 t;
            t.x = f2tf32(v.x); t.y = f2tf32(v.y); t.z = f2tf32(v.z); t.w = f2tf32(v.w);
            ((float4*)(dstarr + (size_t)(off[b] + slot) * H))[lane] = t;
        }
    }

    red[wid * 128 + lane * 4 + 0] = acc.x;
    red[wid * 128 + lane * 4 + 1] = acc.y;
    red[wid * 128 + lane * 4 + 2] = acc.z;
    red[wid * 128 + lane * 4 + 3] = acc.w;
    __syncthreads();
    if (tid < 128) {
        float s = 0.f;
        #pragma unroll
        for (int w = 0; w < 8; w++) s += red[w * 128 + tid];
        atomicAdd(&sums[b * 128 + tid], s);
    }
}

// ---------------------------------------------------------------------------
// Kernel 3: persistent compacted tf32 max-GEMM + fused final loss.
// 148 CTAs; flattened tile space split into equal contiguous chunks.
// Q reloads only on ti change. D double-buffered. 8 warps, 64x32 warp tiles.
// ---------------------------------------------------------------------------
#define STRIDE 132
#define TILE_FLOATS (128 * STRIDE)
#define SMEM_BYTES (3 * TILE_FLOATS * 4)   // 202752 B

__device__ __forceinline__ void cp_tile(float* dst, const float* __restrict__ src, int tid)
{
    #pragma unroll
    for (int i = 0; i < 16; i++) {
        int id  = i * 256 + tid;       // 4096 chunks: 128 rows x 32
        int row = id >> 5;
        int ck  = id & 31;
        CP_ASYNC16(smem_u32(dst + row * STRIDE + ck * 4), src + row * H + ck * 4);
    }
}

__global__ __launch_bounds__(256, 1) void maxgemm_kernel(float* __restrict__ out)
{
    extern __shared__ float sm[];
    float* sQ  = sm;
    float* sD0 = sm + TILE_FLOATS;
    float* sD1 = sm + 2 * TILE_FLOATS;

    __shared__ bool  s_last;
    __shared__ float s_avgq[64], s_avgd[64], s_red[64];

    const int c    = blockIdx.x;     // 0..147
    const int tid  = threadIdx.x;    // 256
    const int wid  = tid >> 5;
    const int lane = tid & 31;
    const int g    = lane >> 2;
    const int tg   = lane & 3;
    const int wm   = wid >> 2;       // 0..1 -> 64 q rows
    const int wn   = wid & 3;        // 0..3 -> 32 d cols

    const int nqt = G.nqt;
    const int ndt = G.ndt;
    const int T   = nqt * ndt;
    const int chunk = (T + NCTA - 1) / NCTA;
    const int i0 = min(c * chunk, T);
    const int i1 = min(i0 + chunk, T);

    if (i0 < i1) {
        int ti_cur = i0 / ndt;
        cp_tile(sQ, G.qt + (size_t)ti_cur * 128 * H, tid);
        cp_tile(sD0, G.dt + (size_t)(i0 % ndt) * 128 * H, tid);
        CP_COMMIT();
        CP_WAIT0();
        __syncthreads();

        const uint32_t* uQ = (const uint32_t*)sQ;

        for (int idx = i0; idx < i1; idx++) {
            const int ti = idx / ndt;
            const int tj = idx % ndt;
            float* curD = ((idx - i0) & 1) ? sD1 : sD0;
            float* nxtD = ((idx - i0) & 1) ? sD0 : sD1;
            if (idx + 1 < i1)
                cp_tile(nxtD, G.dt + (size_t)((idx + 1) % ndt) * 128 * H, tid);
            const uint32_t* uD = (const uint32_t*)curD;

            float acc[4][4][4];
            #pragma unroll
            for (int mt = 0; mt < 4; mt++)
                #pragma unroll
                for (int nb = 0; nb < 4; nb++)
                    #pragma unroll
                    for (int r = 0; r < 4; r++) acc[mt][nb][r] = 0.f;

            #pragma unroll
            for (int ks = 0; ks < 16; ks++) {
                const int k0 = 8 * ks + tg;
                uint32_t A[4][4];
                #pragma unroll
                for (int mt = 0; mt < 4; mt++) {
                    int r0 = (wm * 64 + mt * 16 + g) * STRIDE;
                    A[mt][0] = uQ[r0 + k0];
                    A[mt][1] = uQ[r0 + 8 * STRIDE + k0];
                    A[mt][2] = uQ[r0 + k0 + 4];
                    A[mt][3] = uQ[r0 + 8 * STRIDE + k0 + 4];
                }
                uint32_t B[4][2];
                #pragma unroll
                for (int nb = 0; nb < 4; nb++) {
                    int c0 = (wn * 32 + nb * 8 + g) * STRIDE;
                    B[nb][0] = uD[c0 + k0];
                    B[nb][1] = uD[c0 + k0 + 4];
                }
                #pragma unroll
                for (int mt = 0; mt < 4; mt++)
                    #pragma unroll
                    for (int nb = 0; nb < 4; nb++)
                        mma_tf32(acc[mt][nb][0], acc[mt][nb][1], acc[mt][nb][2], acc[mt][nb][3],
                                 A[mt][0], A[mt][1], A[mt][2], A[mt][3],
                                 B[nb][0], B[nb][1]);
            }

            // ---- epilogue: (8-row group, 32-col group) max -> atomicMax ----
            const int b = G.dlk[tj * 4 + wn];
            #pragma unroll
            for (int mt = 0; mt < 4; mt++) {
                float v0 = -1e30f, v1 = -1e30f;
                #pragma unroll
                for (int nb = 0; nb < 4; nb++) {
                    v0 = fmaxf(v0, fmaxf(acc[mt][nb][0], acc[mt][nb][1]));
                    v1 = fmaxf(v1, fmaxf(acc[mt][nb][2], acc[mt][nb][3]));
                }
                #pragma unroll
                for (int o = 16; o; o >>= 1) {
                    v0 = fmaxf(v0, __shfl_xor_sync(0xffffffffu, v0, o));
                    v1 = fmaxf(v1, __shfl_xor_sync(0xffffffffu, v1, o));
                }
                if (lane == 0) {
                    int gbase = ti * 16 + wm * 8 + mt * 2;
                    if (v0 > 0.f)
                        atomicMax((int*)&G.scores[G.qlk[gbase] * NB + b], __float_as_int(v0));
                    if (v1 > 0.f)
                        atomicMax((int*)&G.scores[G.qlk[gbase + 1] * NB + b], __float_as_int(v1));
                }
            }

            if (idx + 1 < i1) {
                int ti_n = (idx + 1) / ndt;
                if (ti_n != ti_cur) {
                    cp_tile(sQ, G.qt + (size_t)ti_n * 128 * H, tid);
                    ti_cur = ti_n;
                }
                CP_COMMIT();
                CP_WAIT0();
                __syncthreads();
            }
        }
    }

    // ---- last-CTA fused final reduction ----
    __threadfence();
    __syncthreads();
    if (tid == 0) s_last = (atomicAdd(&G.done, 1u) == NCTA - 1u);
    __syncthreads();
    if (!s_last) return;
    if (tid == 0) G.done = 0;

    for (int b = wid; b < NB; b += 8) {
        float4 vq = ((const float4*)G.sumq)[b * 32 + lane];
        float4 vd = ((const float4*)G.sumd)[b * 32 + lane];
        float sq = vq.x*vq.x + vq.y*vq.y + vq.z*vq.z + vq.w*vq.w;
        float sd = vd.x*vd.x + vd.y*vd.y + vd.z*vd.z + vd.w*vd.w;
        #pragma unroll
        for (int o = 16; o; o >>= 1) {
            sq += __shfl_xor_sync(0xffffffffu, sq, o);
            sd += __shfl_xor_sync(0xffffffffu, sd, o);
        }
        if (lane == 0) {
            s_avgq[b] = (sq - (float)SQ) * (1.0f / ((float)SQ * (SQ - 1)));
            s_avgd[b] = (sd - (float)SD) * (1.0f / ((float)SD * (SD - 1)));
        }
    }
    __syncthreads();

    #pragma unroll
    for (int r = 0; r < 8; r++) {
        int a = wid * 8 + r;
        float v0 = __ldcg(&G.scores[a * NB + lane]);
        float v1 = __ldcg(&G.scores[a * NB + 32 + lane]);
        float mx = fmaxf(v0, v1);
        #pragma unroll
        for (int o = 16; o; o >>= 1) mx = fmaxf(mx, __shfl_xor_sync(0xffffffffu, mx, o));
        float sum = expf(v0 - mx) + expf(v1 - mx);
        #pragma unroll
        for (int o = 16; o; o >>= 1) sum += __shfl_xor_sync(0xffffffffu, sum, o);
        if (lane == 0) {
            float diag = __ldcg(&G.scores[a * NB + a]);
            s_red[a] = mx + logf(sum) - diag + s_avgq[a] + s_avgd[a];
        }
    }
    __syncthreads();
    if (tid < 32) {
        float v = s_red[tid] + s_red[tid + 32];
        #pragma unroll
        for (int o = 16; o; o >>= 1) v += __shfl_xor_sync(0xffffffffu, v, o);
        if (tid == 0) out[0] = v * (1.0f / NB);
    }
}

// ---------------------------------------------------------------------------
extern "C" void kernel_launch(void* const* d_in, const int* in_sizes, int n_in,
                              void* d_out, int out_size)
{
    const float* q_emb  = (const float*)d_in[0];
    const float* d_emb  = (const float*)d_in[1];
    const int*   q_mask = (const int*)  d_in[2];
    const int*   d_mask = (const int*)  d_in[3];
    float*       out    = (float*)d_out;

    cudaFuncSetAttribute(maxgemm_kernel,
                         cudaFuncAttributeMaxDynamicSharedMemorySize, SMEM_BYTES);

    count_kernel<<<1, 1024>>>(q_mask, d_mask);
    normscatter<<<576, 256>>>(q_emb, d_emb, q_mask, d_mask);
    maxgemm_kernel<<<NCTA, 256, SMEM_BYTES>>>(out);
}

// round 13
// speedup vs baseline: 4.4748x; 1.2009x over previous
#include <cuda_runtime.h>
#include <math.h>
#include <stdint.h>

#define H    128
#define NB   64
#define SQ   32
#define SD   256
#define NQTOK (NB*SQ)   // 2048
#define NDTOK (NB*SD)   // 16384
#define QLK_N (NQTOK/8)    // 256 max 8-row groups
#define DLK_N (NDTOK/32)   // 512 max 32-col groups
#define NCTA 148

// ---------------- scratch ----------------
// qt/dt zero-init; padding slots never written (deterministic slots, same
// masks each replay). sumq/sumd/scores zeroed in phase 0 each run.
// bar reset by last CTA -> replay deterministic.
struct Scratch {
    float qt[NQTOK*H];
    float dt[NDTOK*H];
    float sumq[NB*H];       // contiguous zero region (2*NB*H + NB*NB floats)
    float sumd[NB*H];
    float scores[NB*NB];
    unsigned bar;
};
__device__ Scratch G;

// ---------------- helpers ----------------
__device__ __forceinline__ uint32_t smem_u32(const void* p) {
    uint32_t a;
    asm("{ .reg .u64 t; cvta.to.shared.u64 t, %1; cvt.u32.u64 %0, t; }" : "=r"(a) : "l"(p));
    return a;
}
__device__ __forceinline__ float f2tf32(float x) {
    uint32_t r;
    asm("cvt.rna.tf32.f32 %0, %1;" : "=r"(r) : "f"(x));
    return __uint_as_float(r);
}
__device__ __forceinline__ void mma_tf32(float& d0, float& d1, float& d2, float& d3,
                                         uint32_t a0, uint32_t a1, uint32_t a2, uint32_t a3,
                                         uint32_t b0, uint32_t b1) {
    asm volatile("mma.sync.aligned.m16n8k8.row.col.f32.tf32.tf32.f32 "
                 "{%0,%1,%2,%3}, {%4,%5,%6,%7}, {%8,%9}, {%0,%1,%2,%3};"
                 : "+f"(d0), "+f"(d1), "+f"(d2), "+f"(d3)
                 : "r"(a0), "r"(a1), "r"(a2), "r"(a3), "r"(b0), "r"(b1));
}
#define CP_ASYNC16(dst, src) \
    asm volatile("cp.async.cg.shared.global [%0], [%1], 16;" :: "r"(dst), "l"(src))
#define CP_COMMIT() asm volatile("cp.async.commit_group;" ::: "memory")
#define CP_WAIT0()  asm volatile("cp.async.wait_group 0;" ::: "memory")

// grid-wide spin barrier: monotonically increasing counter, resident wave.
__device__ __forceinline__ void gbar(unsigned target) {
    __threadfence();
    __syncthreads();
    if (threadIdx.x == 0) {
        atomicAdd(&G.bar, 1u);
        unsigned v;
        do {
            asm volatile("ld.acquire.gpu.global.u32 %0, [%1];"
                         : "=r"(v) : "l"(&G.bar) : "memory");
        } while (v < target);
    }
    __syncthreads();
}

// ---------------- GEMM tiling constants ----------------
#define STRIDE 132
#define TILE_FLOATS (128 * STRIDE)
#define SMEM_BYTES (3 * TILE_FLOATS * 4)   // 202752 B dynamic

__device__ __forceinline__ void cp_tile(float* dst, const float* __restrict__ src, int tid)
{
    #pragma unroll
    for (int i = 0; i < 16; i++) {
        int id  = i * 256 + tid;
        int row = id >> 5;
        int ck  = id & 31;
        CP_ASYNC16(smem_u32(dst + row * STRIDE + ck * 4), src + row * H + ck * 4);
    }
}

// ---------------------------------------------------------------------------
// ONE kernel: phase0 scan -> barA -> phase1 norm+scatter -> barB ->
//             phase2 GEMM -> last-CTA final loss.
// ---------------------------------------------------------------------------
__global__ __launch_bounds__(256, 1) void fused_kernel(
    const float* __restrict__ qin, const float* __restrict__ din,
    const int* __restrict__ qm, const int* __restrict__ dm,
    float* __restrict__ out)
{
    extern __shared__ float sm[];
    __shared__ uint32_t s_qw[64];
    __shared__ uint32_t s_dw[512];
    __shared__ int s_qoff[NB], s_doff[NB];
    __shared__ int s_qlk[QLK_N];
    __shared__ int s_dlk[DLK_N];
    __shared__ int s_nt[2];          // nqt, ndt
    __shared__ float s_red[8 * 128];
    __shared__ float s_avgq[64], s_avgd[64], s_fin[64];
    __shared__ bool s_last;

    const int c    = blockIdx.x;     // 0..147
    const int tid  = threadIdx.x;    // 256
    const int wid  = tid >> 5;
    const int lane = tid & 31;

    // ================= phase 0: redundant mask scan (CTA-local) ============
    for (int i = tid; i < QLK_N; i += 256) s_qlk[i] = 0;
    for (int i = tid; i < DLK_N; i += 256) s_dlk[i] = 0;
    #pragma unroll
    for (int w = wid; w < 64; w += 8) {
        unsigned bal = __ballot_sync(0xffffffffu, qm[w * 32 + lane] != 0);
        if (lane == 0) s_qw[w] = bal;
    }
    #pragma unroll 8
    for (int w = wid; w < 512; w += 8) {
        unsigned bal = __ballot_sync(0xffffffffu, dm[w * 32 + lane] != 0);
        if (lane == 0) s_dw[w] = bal;
    }
    // distributed zeroing of global accumulators (sumq, sumd, scores)
    {
        float* zb = G.sumq;
        for (int i = c * 256 + tid; i < 2 * NB * H + NB * NB; i += NCTA * 256)
            zb[i] = 0.f;
    }
    __syncthreads();

    if (wid == 0) {           // q scan: 2 batches/lane, pad 8
        int c0 = __popc(s_qw[2 * lane]);
        int c1 = __popc(s_qw[2 * lane + 1]);
        int p0 = (c0 + 7) & ~7, p1 = (c1 + 7) & ~7;
        int s = p0 + p1, incl = s;
        #pragma unroll
        for (int o = 1; o < 32; o <<= 1) {
            int t = __shfl_up_sync(0xffffffffu, incl, o);
            if (lane >= o) incl += t;
        }
        int excl = incl - s;
        s_qoff[2 * lane]     = excl;
        s_qoff[2 * lane + 1] = excl + p0;
        int total = __shfl_sync(0xffffffffu, incl, 31);
        if (lane == 0) s_nt[0] = (total + 127) >> 7;
        for (int gI = excl >> 3; gI < (excl + p0) >> 3; gI++) s_qlk[gI] = 2 * lane;
        for (int gI = (excl + p0) >> 3; gI < (excl + p0 + p1) >> 3; gI++) s_qlk[gI] = 2 * lane + 1;
    } else if (wid == 1) {    // d scan: 2 batches/lane, pad 32
        int c0 = 0, c1 = 0;
        #pragma unroll
        for (int k = 0; k < 8; k++) {
            c0 += __popc(s_dw[(2 * lane) * 8 + k]);
            c1 += __popc(s_dw[(2 * lane + 1) * 8 + k]);
        }
        int p0 = (c0 + 31) & ~31, p1 = (c1 + 31) & ~31;
        int s = p0 + p1, incl = s;
        #pragma unroll
        for (int o = 1; o < 32; o <<= 1) {
            int t = __shfl_up_sync(0xffffffffu, incl, o);
            if (lane >= o) incl += t;
        }
        int excl = incl - s;
        s_doff[2 * lane]     = excl;
        s_doff[2 * lane + 1] = excl + p0;
        int total = __shfl_sync(0xffffffffu, incl, 31);
        if (lane == 0) s_nt[1] = (total + 127) >> 7;
        for (int gI = excl >> 5; gI < (excl + p0) >> 5; gI++) s_dlk[gI] = 2 * lane;
        for (int gI = (excl + p0) >> 5; gI < (excl + p0 + p1) >> 5; gI++) s_dlk[gI] = 2 * lane + 1;
    }

    // ================= barrier A (zeroing visible) ==========================
    gbar(NCTA);

    // ================= phase 1: normalize + deterministic scatter ===========
    for (int cc = c; cc < 576; cc += NCTA) {
        const float* in; float* sums; float* dst;
        int b, tokbase, off, prefPrev, ibb;
        uint32_t word;
        if (cc < 64) {
            b = cc; tokbase = cc * 32; in = qin; sums = G.sumq; dst = G.qt;
            word = s_qw[cc]; off = s_qoff[b]; prefPrev = 0; ibb = 0;
        } else {
            int dd = cc - 64; b = dd >> 3; int ci = dd & 7;
            tokbase = dd * 32; in = din; sums = G.sumd; dst = G.dt;
            word = s_dw[dd]; off = s_doff[b];
            prefPrev = 0;
            for (int k = 0; k < ci; k++) prefPrev += __popc(s_dw[b * 8 + k]);
            ibb = 0;
        }
        (void)ibb;

        float4 acc = make_float4(0.f, 0.f, 0.f, 0.f);
        #pragma unroll
        for (int j4 = 0; j4 < 4; j4++) {
            const int j   = wid * 4 + j4;         // in-chunk token 0..31
            const int tok = tokbase + j;
            float4 v = ((const float4*)in)[tok * 32 + lane];
            float ss = v.x*v.x + v.y*v.y + v.z*v.z + v.w*v.w;
            #pragma unroll
            for (int o = 16; o; o >>= 1) ss += __shfl_xor_sync(0xffffffffu, ss, o);
            float scale = 1.0f / fmaxf(sqrtf(ss), 1e-12f);
            v.x *= scale; v.y *= scale; v.z *= scale; v.w *= scale;
            acc.x += v.x; acc.y += v.y; acc.z += v.z; acc.w += v.w;

            if ((word >> j) & 1u) {
                int slot = off + prefPrev + __popc(word & ((1u << j) - 1u));
                float4 t;
                t.x = f2tf32(v.x); t.y = f2tf32(v.y);
                t.z = f2tf32(v.z); t.w = f2tf32(v.w);
                ((float4*)(dst + (size_t)slot * H))[lane] = t;
            }
        }

        s_red[wid * 128 + lane * 4 + 0] = acc.x;
        s_red[wid * 128 + lane * 4 + 1] = acc.y;
        s_red[wid * 128 + lane * 4 + 2] = acc.z;
        s_red[wid * 128 + lane * 4 + 3] = acc.w;
        __syncthreads();
        if (tid < 128) {
            float s = 0.f;
            #pragma unroll
            for (int w = 0; w < 8; w++) s += s_red[w * 128 + tid];
            atomicAdd(&sums[b * 128 + tid], s);
        }
        __syncthreads();
    }

    // ================= barrier B (compacted data visible) ===================
    gbar(2 * NCTA);

    // ================= phase 2: persistent tf32 max-GEMM ====================
    {
        float* sQ  = sm;
        float* sD0 = sm + TILE_FLOATS;
        float* sD1 = sm + 2 * TILE_FLOATS;
        const int g  = lane >> 2;
        const int tg = lane & 3;
        const int wm = wid >> 2;       // 0..1 -> 64 q rows
        const int wn = wid & 3;        // 0..3 -> 32 d cols

        const int nqt = s_nt[0];
        const int ndt = s_nt[1];
        const int T   = nqt * ndt;
        const int chunk = (T + NCTA - 1) / NCTA;
        const int i0 = min(c * chunk, T);
        const int i1 = min(i0 + chunk, T);

        if (i0 < i1) {
            int ti_cur = i0 / ndt;
            cp_tile(sQ, G.qt + (size_t)ti_cur * 128 * H, tid);
            cp_tile(sD0, G.dt + (size_t)(i0 % ndt) * 128 * H, tid);
            CP_COMMIT();
            CP_WAIT0();
            __syncthreads();

            const uint32_t* uQ = (const uint32_t*)sQ;

            for (int idx = i0; idx < i1; idx++) {
                const int ti = idx / ndt;
                const int tj = idx % ndt;
                float* curD = ((idx - i0) & 1) ? sD1 : sD0;
                float* nxtD = ((idx - i0) & 1) ? sD0 : sD1;
                if (idx + 1 < i1)
                    cp_tile(nxtD, G.dt + (size_t)((idx + 1) % ndt) * 128 * H, tid);
                const uint32_t* uD = (const uint32_t*)curD;

                float acc[4][4][4];
                #pragma unroll
                for (int mt = 0; mt < 4; mt++)
                    #pragma unroll
                    for (int nb = 0; nb < 4; nb++)
                        #pragma unroll
                        for (int r = 0; r < 4; r++) acc[mt][nb][r] = 0.f;

                #pragma unroll
                for (int ks = 0; ks < 16; ks++) {
                    const int k0 = 8 * ks + tg;
                    uint32_t A[4][4];
                    #pragma unroll
                    for (int mt = 0; mt < 4; mt++) {
                        int r0 = (wm * 64 + mt * 16 + g) * STRIDE;
                        A[mt][0] = uQ[r0 + k0];
                        A[mt][1] = uQ[r0 + 8 * STRIDE + k0];
                        A[mt][2] = uQ[r0 + k0 + 4];
                        A[mt][3] = uQ[r0 + 8 * STRIDE + k0 + 4];
                    }
                    uint32_t B[4][2];
                    #pragma unroll
                    for (int nb = 0; nb < 4; nb++) {
                        int c0 = (wn * 32 + nb * 8 + g) * STRIDE;
                        B[nb][0] = uD[c0 + k0];
                        B[nb][1] = uD[c0 + k0 + 4];
                    }
                    #pragma unroll
                    for (int mt = 0; mt < 4; mt++)
                        #pragma unroll
                        for (int nb = 0; nb < 4; nb++)
                            mma_tf32(acc[mt][nb][0], acc[mt][nb][1], acc[mt][nb][2], acc[mt][nb][3],
                                     A[mt][0], A[mt][1], A[mt][2], A[mt][3],
                                     B[nb][0], B[nb][1]);
                }

                // epilogue: (8-row group, 32-col group) max -> atomicMax
                const int b = s_dlk[tj * 4 + wn];
                #pragma unroll
                for (int mt = 0; mt < 4; mt++) {
                    float v0 = -1e30f, v1 = -1e30f;
                    #pragma unroll
                    for (int nb = 0; nb < 4; nb++) {
                        v0 = fmaxf(v0, fmaxf(acc[mt][nb][0], acc[mt][nb][1]));
                        v1 = fmaxf(v1, fmaxf(acc[mt][nb][2], acc[mt][nb][3]));
                    }
                    #pragma unroll
                    for (int o = 16; o; o >>= 1) {
                        v0 = fmaxf(v0, __shfl_xor_sync(0xffffffffu, v0, o));
                        v1 = fmaxf(v1, __shfl_xor_sync(0xffffffffu, v1, o));
                    }
                    if (lane == 0) {
                        int gbase = ti * 16 + wm * 8 + mt * 2;
                        if (v0 > 0.f)
                            atomicMax((int*)&G.scores[s_qlk[gbase] * NB + b], __float_as_int(v0));
                        if (v1 > 0.f)
                            atomicMax((int*)&G.scores[s_qlk[gbase + 1] * NB + b], __float_as_int(v1));
                    }
                }

                if (idx + 1 < i1) {
                    int ti_n = (idx + 1) / ndt;
                    if (ti_n != ti_cur) {
                        cp_tile(sQ, G.qt + (size_t)ti_n * 128 * H, tid);
                        ti_cur = ti_n;
                    }
                    CP_COMMIT();
                    CP_WAIT0();
                    __syncthreads();
                }
            }
        }
    }

    // ================= phase 3: last-CTA final loss =========================
    __threadfence();
    __syncthreads();
    if (tid == 0) s_last = (atomicAdd(&G.bar, 1u) == 3u * NCTA - 1u);
    __syncthreads();
    if (!s_last) return;
    if (tid == 0) G.bar = 0;   // reset for graph replay determinism

    for (int b = wid; b < NB; b += 8) {
        float4 vq = ((const float4*)G.sumq)[b * 32 + lane];
        float4 vd = ((const float4*)G.sumd)[b * 32 + lane];
        float sq = vq.x*vq.x + vq.y*vq.y + vq.z*vq.z + vq.w*vq.w;
        float sd = vd.x*vd.x + vd.y*vd.y + vd.z*vd.z + vd.w*vd.w;
        #pragma unroll
        for (int o = 16; o; o >>= 1) {
            sq += __shfl_xor_sync(0xffffffffu, sq, o);
            sd += __shfl_xor_sync(0xffffffffu, sd, o);
        }
        if (lane == 0) {
            s_avgq[b] = (sq - (float)SQ) * (1.0f / ((float)SQ * (SQ - 1)));
            s_avgd[b] = (sd - (float)SD) * (1.0f / ((float)SD * (SD - 1)));
        }
    }
    __syncthreads();

    #pragma unroll
    for (int r = 0; r < 8; r++) {
        int a = wid * 8 + r;
        float v0 = __ldcg(&G.scores[a * NB + lane]);
        float v1 = __ldcg(&G.scores[a * NB + 32 + lane]);
        float mx = fmaxf(v0, v1);
        #pragma unroll
        for (int o = 16; o; o >>= 1) mx = fmaxf(mx, __shfl_xor_sync(0xffffffffu, mx, o));
        float sum = expf(v0 - mx) + expf(v1 - mx);
        #pragma unroll
        for (int o = 16; o; o >>= 1) sum += __shfl_xor_sync(0xffffffffu, sum, o);
        if (lane == 0) {
            float diag = __ldcg(&G.scores[a * NB + a]);
            s_fin[a] = mx + logf(sum) - diag + s_avgq[a] + s_avgd[a];
        }
    }
    __syncthreads();
    if (tid < 32) {
        float v = s_fin[tid] + s_fin[tid + 32];
        #pragma unroll
        for (int o = 16; o; o >>= 1) v += __shfl_xor_sync(0xffffffffu, v, o);
        if (tid == 0) out[0] = v * (1.0f / NB);
    }
}

// ---------------------------------------------------------------------------
extern "C" void kernel_launch(void* const* d_in, const int* in_sizes, int n_in,
                              void* d_out, int out_size)
{
    const float* q_emb  = (const float*)d_in[0];
    const float* d_emb  = (const float*)d_in[1];
    const int*   q_mask = (const int*)  d_in[2];
    const int*   d_mask = (const int*)  d_in[3];
    float*       out    = (float*)d_out;

    cudaFuncSetAttribute(fused_kernel,
                         cudaFuncAttributeMaxDynamicSharedMemorySize, SMEM_BYTES);

    fused_kernel<<<NCTA, 256, SMEM_BYTES>>>(q_emb, d_emb, q_mask, d_mask, out);
}